// round 6
// baseline (speedup 1.0000x reference)
#include <cuda_runtime.h>
#include <cuda_bf16.h>
#include <math.h>
#include <stdint.h>

#define BB   2
#define SS   2048
#define HIDD 2048
#define NH   16
#define HD   128
#define NKV  4
#define MR   (BB*SS)          // 4096
#define KVD  (NKV*HD)         // 512

// -------- scratch (device globals; no allocation allowed) --------
__device__ float g_tmpq[MR * HIDD];
__device__ float g_tmpk[MR * KVD];
__device__ float g_tmpv[MR * KVD];
__device__ float g_q[BB * NH * SS * HD];
__device__ float g_k[BB * NKV * SS * HD];
__device__ float g_v[BB * NKV * SS * HD];
__device__ float g_ctx[MR * HIDD];
__device__ __nv_bfloat16 g_Ah[MR * HIDD];        // A split hi
__device__ __nv_bfloat16 g_Al[MR * HIDD];        // A split lo
__device__ __nv_bfloat16 g_Wh[HIDD * HIDD];      // W^T split hi [N,K]
__device__ __nv_bfloat16 g_Wl[HIDD * HIDD];      // W^T split lo [N,K]

// ================= helpers =================
__device__ __forceinline__ uint32_t smem_u32(const void* p) {
    uint32_t a;
    asm("{ .reg .u64 t; cvta.to.shared.u64 t, %1; cvt.u32.u64 %0, t; }"
        : "=r"(a) : "l"(p));
    return a;
}

#define CP_ASYNC16(smem, gptr) \
    asm volatile("cp.async.cg.shared.global [%0], [%1], 16;" \
        :: "r"(smem), "l"(gptr))
#define CP_COMMIT() asm volatile("cp.async.commit_group;" ::: "memory")
#define CP_WAIT(n)  asm volatile("cp.async.wait_group %0;" :: "n"(n) : "memory")

#define LDSM4(r0, r1, r2, r3, addr) \
    asm volatile("ldmatrix.sync.aligned.m8n8.x4.shared.b16 {%0,%1,%2,%3}, [%4];" \
        : "=r"(r0), "=r"(r1), "=r"(r2), "=r"(r3) : "r"(addr))

#define MMA16816(c, a, b) \
    asm volatile("mma.sync.aligned.m16n8k16.row.col.f32.bf16.bf16.f32 " \
        "{%0,%1,%2,%3},{%4,%5,%6,%7},{%8,%9},{%0,%1,%2,%3};" \
        : "+f"((c)[0]), "+f"((c)[1]), "+f"((c)[2]), "+f"((c)[3]) \
        : "r"((a)[0]), "r"((a)[1]), "r"((a)[2]), "r"((a)[3]), \
          "r"((b)[0]), "r"((b)[1]))

// ============================================================
// Split kernels
// ============================================================
__global__ __launch_bounds__(256) void asplit(const float* __restrict__ A,
                                              __nv_bfloat16* __restrict__ Oh,
                                              __nv_bfloat16* __restrict__ Ol)
{
    size_t i = ((size_t)blockIdx.x * 256 + threadIdx.x) * 4;
    float4 v = *(const float4*)(A + i);
    __nv_bfloat16 h0 = __float2bfloat16(v.x), h1 = __float2bfloat16(v.y),
                  h2 = __float2bfloat16(v.z), h3 = __float2bfloat16(v.w);
    __nv_bfloat16 l0 = __float2bfloat16(v.x - __bfloat162float(h0));
    __nv_bfloat16 l1 = __float2bfloat16(v.y - __bfloat162float(h1));
    __nv_bfloat16 l2 = __float2bfloat16(v.z - __bfloat162float(h2));
    __nv_bfloat16 l3 = __float2bfloat16(v.w - __bfloat162float(h3));
    union { __nv_bfloat162 b[2]; uint2 u; } H, L;
    H.b[0] = __halves2bfloat162(h0, h1); H.b[1] = __halves2bfloat162(h2, h3);
    L.b[0] = __halves2bfloat162(l0, l1); L.b[1] = __halves2bfloat162(l2, l3);
    *(uint2*)(Oh + i) = H.u;
    *(uint2*)(Ol + i) = L.u;
}

// W [Kd,Nd] fp32 -> Wt [Nd,Kd] bf16 hi/lo
__global__ __launch_bounds__(256) void wsplit(const float* __restrict__ W,
                                              __nv_bfloat16* __restrict__ Oh,
                                              __nv_bfloat16* __restrict__ Ol,
                                              int Kd, int Nd)
{
    __shared__ float s[32][33];
    int k0 = blockIdx.y * 32, n0 = blockIdx.x * 32;
    int r = threadIdx.x >> 5, c = threadIdx.x & 31;
    #pragma unroll
    for (int j = 0; j < 4; j++)
        s[r + 8 * j][c] = W[(size_t)(k0 + r + 8 * j) * Nd + n0 + c];
    __syncthreads();
    #pragma unroll
    for (int j = 0; j < 4; j++) {
        float v = s[c][r + 8 * j];
        __nv_bfloat16 h = __float2bfloat16(v);
        __nv_bfloat16 l = __float2bfloat16(v - __bfloat162float(h));
        size_t o = (size_t)(n0 + r + 8 * j) * Kd + k0 + c;
        Oh[o] = h; Ol[o] = l;
    }
}

// ============================================================
// mma.sync split-bf16 GEMM: C[M,N] = (Ah+Al)[M,K] @ ((Wh+Wl)[N,K])^T + bias
// BM=BN=128, BK=32, 256 threads (8 warps, 4x2 warp grid, 32x64 warp tile).
// 3 passes: AhBh + AhBl + AlBh. cp.async double-buffered.
// K fixed = HIDD = 2048.
// ============================================================
#define GBK      32
#define NCH      (HIDD / GBK)       // 64
#define APITCH   40                  // padded row pitch (bf16): 80 bytes
#define TILE_B   (128 * APITCH * 2)  // 10240
#define STAGE_B  (4 * TILE_B)        // Ah, Al, Bh, Bl = 40960
#define GEMM_SMEM (2 * STAGE_B)      // 81920

__global__ __launch_bounds__(256)
void gemm_mma_split(const __nv_bfloat16* __restrict__ Ah,
                    const __nv_bfloat16* __restrict__ Al,
                    const __nv_bfloat16* __restrict__ Bh,
                    const __nv_bfloat16* __restrict__ Bl,
                    const float* __restrict__ bias,
                    float* __restrict__ C, int N)
{
    extern __shared__ char smem[];
    const uint32_t smem_base = smem_u32(smem);

    const int tid  = threadIdx.x;
    const int lane = tid & 31;
    const int warp = tid >> 5;
    const int bm = blockIdx.y * 128;
    const int bn = blockIdx.x * 128;

    const int wm = warp >> 1;          // 0..3
    const int wn = warp & 1;           // 0..1
    const int m0 = wm * 32;
    const int n0 = wn * 64;

    // ---- global->smem load mapping: 512 16B-chunks per tile ----
    const int cc0 = tid;               // chunks tid and tid+256
    const int r0c = cc0 >> 2, c0c = cc0 & 3;
    const int cc1 = tid + 256;
    const int r1c = cc1 >> 2, c1c = cc1 & 3;

    float acc[2][8][4];
    #pragma unroll
    for (int mt = 0; mt < 2; mt++)
        #pragma unroll
        for (int nf = 0; nf < 8; nf++)
            #pragma unroll
            for (int q = 0; q < 4; q++) acc[mt][nf][q] = 0.f;

    // ldmatrix lane addressing (byte offsets within a tile)
    const int a_row = m0 + (lane & 15);
    const int a_c8  = (lane >> 4);           // 0 or 1  (k offset 0/8)
    const int b_row = n0 + (lane & 7) + ((lane >> 4) << 3);
    const int b_c8  = (lane >> 3) & 1;

    auto load_stage = [&](int s, int k0) {
        uint32_t sb = smem_base + s * STAGE_B;
        const __nv_bfloat16* gA_h = Ah + (size_t)(bm + r0c) * HIDD + k0 + c0c * 8;
        const __nv_bfloat16* gA_l = Al + (size_t)(bm + r0c) * HIDD + k0 + c0c * 8;
        const __nv_bfloat16* gB_h = Bh + (size_t)(bn + r0c) * HIDD + k0 + c0c * 8;
        const __nv_bfloat16* gB_l = Bl + (size_t)(bn + r0c) * HIDD + k0 + c0c * 8;
        uint32_t so0 = (uint32_t)(r0c * 80 + c0c * 16);
        CP_ASYNC16(sb + so0,              gA_h);
        CP_ASYNC16(sb + TILE_B + so0,     gA_l);
        CP_ASYNC16(sb + 2 * TILE_B + so0, gB_h);
        CP_ASYNC16(sb + 3 * TILE_B + so0, gB_l);
        const __nv_bfloat16* gA_h1 = Ah + (size_t)(bm + r1c) * HIDD + k0 + c1c * 8;
        const __nv_bfloat16* gA_l1 = Al + (size_t)(bm + r1c) * HIDD + k0 + c1c * 8;
        const __nv_bfloat16* gB_h1 = Bh + (size_t)(bn + r1c) * HIDD + k0 + c1c * 8;
        const __nv_bfloat16* gB_l1 = Bl + (size_t)(bn + r1c) * HIDD + k0 + c1c * 8;
        uint32_t so1 = (uint32_t)(r1c * 80 + c1c * 16);
        CP_ASYNC16(sb + so1,              gA_h1);
        CP_ASYNC16(sb + TILE_B + so1,     gA_l1);
        CP_ASYNC16(sb + 2 * TILE_B + so1, gB_h1);
        CP_ASYNC16(sb + 3 * TILE_B + so1, gB_l1);
    };

    // prologue
    load_stage(0, 0);
    CP_COMMIT();

    for (int ch = 0; ch < NCH; ch++) {
        const int s = ch & 1;
        if (ch + 1 < NCH) {
            load_stage(s ^ 1, (ch + 1) * GBK);
            CP_COMMIT();
            CP_WAIT(1);
        } else {
            CP_WAIT(0);
        }
        __syncthreads();

        const uint32_t sb = smem_base + s * STAGE_B;
        #pragma unroll
        for (int kk = 0; kk < 2; kk++) {
            const int kbyte = (kk * 16 + a_c8 * 8) * 2;
            uint32_t ah[2][4], al[2][4];
            #pragma unroll
            for (int mt = 0; mt < 2; mt++) {
                uint32_t aaddr = sb + (uint32_t)((a_row + mt * 16) * 80 + kbyte);
                LDSM4(ah[mt][0], ah[mt][1], ah[mt][2], ah[mt][3], aaddr);
                LDSM4(al[mt][0], al[mt][1], al[mt][2], al[mt][3], aaddr + TILE_B);
            }
            const int kbyteB = (kk * 16 + b_c8 * 8) * 2;
            #pragma unroll
            for (int nf2 = 0; nf2 < 4; nf2++) {
                uint32_t baddr = sb + 2 * TILE_B
                               + (uint32_t)((b_row + nf2 * 16) * 80 + kbyteB);
                uint32_t bh[2][2], bl[2][2];
                LDSM4(bh[0][0], bh[0][1], bh[1][0], bh[1][1], baddr);
                LDSM4(bl[0][0], bl[0][1], bl[1][0], bl[1][1], baddr + TILE_B);
                #pragma unroll
                for (int half = 0; half < 2; half++) {
                    const int nf = nf2 * 2 + half;
                    #pragma unroll
                    for (int mt = 0; mt < 2; mt++) {
                        MMA16816(acc[mt][nf], ah[mt], bh[half]);
                        MMA16816(acc[mt][nf], ah[mt], bl[half]);
                        MMA16816(acc[mt][nf], al[mt], bh[half]);
                    }
                }
            }
        }
        __syncthreads();
    }

    // epilogue: bias + store
    #pragma unroll
    for (int mt = 0; mt < 2; mt++) {
        int grow = bm + m0 + mt * 16 + (lane >> 2);
        #pragma unroll
        for (int nf = 0; nf < 8; nf++) {
            int gcol = bn + n0 + nf * 8 + (lane & 3) * 2;
            float2 bv = *(const float2*)(bias + gcol);
            float2 o0, o1;
            o0.x = acc[mt][nf][0] + bv.x;
            o0.y = acc[mt][nf][1] + bv.y;
            o1.x = acc[mt][nf][2] + bv.x;
            o1.y = acc[mt][nf][3] + bv.y;
            *(float2*)(C + (size_t)grow * N + gcol)       = o0;
            *(float2*)(C + (size_t)(grow + 8) * N + gcol) = o1;
        }
    }
}

// ============================================================
// RoPE + transpose
// ============================================================
template <int NHEADS>
__global__ void rope_transpose(const float* __restrict__ tmp,
                               const float* __restrict__ cs,
                               const float* __restrict__ sn,
                               float* __restrict__ out)
{
    int idx = blockIdx.x * blockDim.x + threadIdx.x;
    const int TOT = BB * SS * NHEADS * (HD / 2);
    if (idx >= TOT) return;
    int p = idx & 63;
    int h = (idx >> 6) % NHEADS;
    int rest = idx / (64 * NHEADS);
    int s = rest % SS;
    int b = rest / SS;

    size_t irow = (size_t)(b * SS + s) * (NHEADS * HD) + h * HD + 2 * p;
    float xe = tmp[irow];
    float xo = tmp[irow + 1];
    float c = cs[s * 64 + p];
    float si = sn[s * 64 + p];
    float re = xe * c - xo * si;
    float im = xe * si + xo * c;
    size_t o = ((size_t)(b * NHEADS + h) * SS + s) * HD + 2 * p;
    out[o] = re;
    out[o + 1] = im;
}

__global__ void transpose_v(const float* __restrict__ tmp, float* __restrict__ out)
{
    int idx = blockIdx.x * blockDim.x + threadIdx.x;
    if (idx >= BB * SS * NKV * HD) return;
    int d = idx & 127;
    int h = (idx >> 7) & 3;
    int s = (idx >> 9) & 2047;
    int b = idx >> 20;
    out[((size_t)(b * NKV + h) * SS + s) * HD + d] =
        tmp[(size_t)(b * SS + s) * KVD + h * HD + d];
}

// ============================================================
// Flash-style causal attention (fp32, known-good from R0)
// ============================================================
#define QT 64
#define KT 64
#define DP 132
#define SP 68
#define ATT_SMEM_FLOATS (3*QT*DP + QT*SP + 3*QT)
#define ATT_SMEM_BYTES  (ATT_SMEM_FLOATS*4)

__global__ __launch_bounds__(256, 1) void attn_kernel(
    const float* __restrict__ Qg, const float* __restrict__ Kg,
    const float* __restrict__ Vg, float* __restrict__ ctx)
{
    extern __shared__ float sm[];
    float* Qs   = sm;
    float* Ks   = Qs + QT * DP;
    float* Vs   = Ks + KT * DP;
    float* Ssm  = Vs + KT * DP;
    float* m_sh = Ssm + QT * SP;
    float* l_sh = m_sh + QT;
    float* a_sh = l_sh + QT;

    const int tid = threadIdx.x;
    const int qb = blockIdx.x;
    const int h  = blockIdx.y;
    const int b  = blockIdx.z;
    const int kvh = h >> 2;

    const float* Qbase = Qg + ((size_t)(b * NH + h) * SS + qb * QT) * HD;
    const float* Kbase = Kg + ((size_t)(b * NKV + kvh) * SS) * HD;
    const float* Vbase = Vg + ((size_t)(b * NKV + kvh) * SS) * HD;

    #pragma unroll
    for (int it = 0; it < 8; it++) {
        int lin = tid + it * 256;
        int row = lin >> 5;
        int d4  = (lin & 31) * 4;
        *(float4*)&Qs[row * DP + d4] = *(const float4*)(Qbase + row * HD + d4);
    }
    if (tid < QT) { m_sh[tid] = -1e30f; l_sh[tid] = 0.f; }

    const int warp  = tid >> 5;
    const int warpR = warp >> 1;
    const int warpC = warp & 1;
    const int lr = (tid & 31) >> 3;
    const int lc = tid & 7;
    const int qr0 = warpR * 16 + lr;
    const int kc0 = warpC * 32 + lc;

    const int tr = tid >> 4;
    const int tc = tid & 15;

    float o[4][8];
    #pragma unroll
    for (int i = 0; i < 4; i++)
        #pragma unroll
        for (int j = 0; j < 8; j++) o[i][j] = 0.f;

    const float scale = 0.08838834764831845f;
    const int nkb = qb + 1;

    for (int kb = 0; kb < nkb; kb++) {
        __syncthreads();
        #pragma unroll
        for (int it = 0; it < 8; it++) {
            int lin = tid + it * 256;
            int row = lin >> 5;
            int d4  = (lin & 31) * 4;
            *(float4*)&Ks[row * DP + d4] =
                *(const float4*)(Kbase + (size_t)(kb * KT + row) * HD + d4);
        }
        __syncthreads();

        float acc[4][4];
        #pragma unroll
        for (int i = 0; i < 4; i++)
            #pragma unroll
            for (int j = 0; j < 4; j++) acc[i][j] = 0.f;

        #pragma unroll 8
        for (int d0 = 0; d0 < HD; d0 += 4) {
            float4 qf[4], kf[4];
            #pragma unroll
            for (int i = 0; i < 4; i++)
                qf[i] = *(const float4*)&Qs[(qr0 + 4 * i) * DP + d0];
            #pragma unroll
            for (int j = 0; j < 4; j++)
                kf[j] = *(const float4*)&Ks[(kc0 + 8 * j) * DP + d0];
            #pragma unroll
            for (int i = 0; i < 4; i++)
                #pragma unroll
                for (int j = 0; j < 4; j++)
                    acc[i][j] += qf[i].x * kf[j].x + qf[i].y * kf[j].y
                               + qf[i].z * kf[j].z + qf[i].w * kf[j].w;
        }
        #pragma unroll
        for (int i = 0; i < 4; i++) {
            int qg = qb * QT + qr0 + 4 * i;
            #pragma unroll
            for (int j = 0; j < 4; j++) {
                int kg = kb * KT + kc0 + 8 * j;
                float v = acc[i][j] * scale;
                if (kg > qg) v = -1e30f;
                Ssm[(qr0 + 4 * i) * SP + kc0 + 8 * j] = v;
            }
        }
        __syncthreads();

        #pragma unroll
        for (int it = 0; it < 8; it++) {
            int lin = tid + it * 256;
            int row = lin >> 5;
            int d4  = (lin & 31) * 4;
            *(float4*)&Vs[row * DP + d4] =
                *(const float4*)(Vbase + (size_t)(kb * KT + row) * HD + d4);
        }

        {
            int r  = tid >> 2;
            int c0 = (tid & 3) * 16;
            float mloc = -1e30f;
            #pragma unroll
            for (int c = 0; c < 16; c++) mloc = fmaxf(mloc, Ssm[r * SP + c0 + c]);
            mloc = fmaxf(mloc, __shfl_xor_sync(0xffffffffu, mloc, 1));
            mloc = fmaxf(mloc, __shfl_xor_sync(0xffffffffu, mloc, 2));
            float mold = m_sh[r];
            float mnew = fmaxf(mold, mloc);
            float sum = 0.f;
            #pragma unroll
            for (int c = 0; c < 16; c++) {
                float p = __expf(Ssm[r * SP + c0 + c] - mnew);
                Ssm[r * SP + c0 + c] = p;
                sum += p;
            }
            sum += __shfl_xor_sync(0xffffffffu, sum, 1);
            sum += __shfl_xor_sync(0xffffffffu, sum, 2);
            if ((tid & 3) == 0) {
                float alpha = __expf(mold - mnew);
                l_sh[r] = l_sh[r] * alpha + sum;
                m_sh[r] = mnew;
                a_sh[r] = alpha;
            }
        }
        __syncthreads();

        float al4[4];
        #pragma unroll
        for (int i = 0; i < 4; i++) al4[i] = a_sh[tr * 4 + i];
        #pragma unroll
        for (int i = 0; i < 4; i++)
            #pragma unroll
            for (int j = 0; j < 8; j++) o[i][j] *= al4[i];

        #pragma unroll 4
        for (int kk = 0; kk < KT; kk++) {
            float pv[4];
            #pragma unroll
            for (int i = 0; i < 4; i++) pv[i] = Ssm[(tr * 4 + i) * SP + kk];
            float vv[8];
            #pragma unroll
            for (int j = 0; j < 8; j++) vv[j] = Vs[kk * DP + tc + 16 * j];
            #pragma unroll
            for (int i = 0; i < 4; i++)
                #pragma unroll
                for (int j = 0; j < 8; j++)
                    o[i][j] += pv[i] * vv[j];
        }
    }
    __syncthreads();

    #pragma unroll
    for (int i = 0; i < 4; i++) {
        int srow = qb * QT + tr * 4 + i;
        float inv = 1.f / l_sh[tr * 4 + i];
        size_t base = (size_t)(b * SS + srow) * HIDD + h * HD + tc;
        #pragma unroll
        for (int j = 0; j < 8; j++)
            ctx[base + 16 * j] = o[i][j] * inv;
    }
}

// ============================================================
// launch
// ============================================================
extern "C" void kernel_launch(void* const* d_in, const int* in_sizes, int n_in,
                              void* d_out, int out_size)
{
    const float* query = (const float*)d_in[0];
    const float* key   = (const float*)d_in[1];
    const float* value = (const float*)d_in[2];
    const float* fcos  = (const float*)d_in[4];
    const float* fsin  = (const float*)d_in[5];
    const float* Wq = (const float*)d_in[6];
    const float* bq = (const float*)d_in[7];
    const float* Wk = (const float*)d_in[8];
    const float* bk = (const float*)d_in[9];
    const float* Wv = (const float*)d_in[10];
    const float* bv = (const float*)d_in[11];
    const float* Wo = (const float*)d_in[12];
    const float* bo = (const float*)d_in[13];
    float* out = (float*)d_out;

    float *tmpq, *tmpk, *tmpv, *qT, *kT, *vT, *ctx;
    __nv_bfloat16 *Aph, *Apl, *Wph, *Wpl;
    cudaGetSymbolAddress((void**)&tmpq, g_tmpq);
    cudaGetSymbolAddress((void**)&tmpk, g_tmpk);
    cudaGetSymbolAddress((void**)&tmpv, g_tmpv);
    cudaGetSymbolAddress((void**)&qT,   g_q);
    cudaGetSymbolAddress((void**)&kT,   g_k);
    cudaGetSymbolAddress((void**)&vT,   g_v);
    cudaGetSymbolAddress((void**)&ctx,  g_ctx);
    cudaGetSymbolAddress((void**)&Aph,  g_Ah);
    cudaGetSymbolAddress((void**)&Apl,  g_Al);
    cudaGetSymbolAddress((void**)&Wph,  g_Wh);
    cudaGetSymbolAddress((void**)&Wpl,  g_Wl);

    cudaFuncSetAttribute(gemm_mma_split,
                         cudaFuncAttributeMaxDynamicSharedMemorySize, GEMM_SMEM);
    cudaFuncSetAttribute(attn_kernel,
                         cudaFuncAttributeMaxDynamicSharedMemorySize, ATT_SMEM_BYTES);

    const int ASPLIT_BLKS = (MR * HIDD) / 1024;   // 8192

    // ---- Q projection ----
    asplit<<<ASPLIT_BLKS, 256>>>(query, Aph, Apl);
    wsplit<<<dim3(HIDD / 32, HIDD / 32), 256>>>(Wq, Wph, Wpl, HIDD, HIDD);
    gemm_mma_split<<<dim3(HIDD / 128, MR / 128), 256, GEMM_SMEM>>>(
        Aph, Apl, Wph, Wpl, bq, tmpq, HIDD);

    // ---- K projection ----
    asplit<<<ASPLIT_BLKS, 256>>>(key, Aph, Apl);
    wsplit<<<dim3(KVD / 32, HIDD / 32), 256>>>(Wk, Wph, Wpl, HIDD, KVD);
    gemm_mma_split<<<dim3(KVD / 128, MR / 128), 256, GEMM_SMEM>>>(
        Aph, Apl, Wph, Wpl, bk, tmpk, KVD);

    // ---- V projection ----
    asplit<<<ASPLIT_BLKS, 256>>>(value, Aph, Apl);
    wsplit<<<dim3(KVD / 32, HIDD / 32), 256>>>(Wv, Wph, Wpl, HIDD, KVD);
    gemm_mma_split<<<dim3(KVD / 128, MR / 128), 256, GEMM_SMEM>>>(
        Aph, Apl, Wph, Wpl, bv, tmpv, KVD);

    // ---- RoPE / transposes ----
    rope_transpose<NH><<<(BB * SS * NH * 64) / 256, 256>>>(tmpq, fcos, fsin, qT);
    rope_transpose<NKV><<<(BB * SS * NKV * 64) / 256, 256>>>(tmpk, fcos, fsin, kT);
    transpose_v<<<(BB * SS * NKV * HD) / 256, 256>>>(tmpv, vT);

    // ---- attention ----
    attn_kernel<<<dim3(SS / QT, NH, BB), 256, ATT_SMEM_BYTES>>>(qT, kT, vT, ctx);

    // ---- O projection ----
    asplit<<<ASPLIT_BLKS, 256>>>(ctx, Aph, Apl);
    wsplit<<<dim3(HIDD / 32, HIDD / 32), 256>>>(Wo, Wph, Wpl, HIDD, HIDD);
    gemm_mma_split<<<dim3(HIDD / 128, MR / 128), 256, GEMM_SMEM>>>(
        Aph, Apl, Wph, Wpl, bo, out, HIDD);
}

// round 9
// speedup vs baseline: 2.3372x; 2.3372x over previous
#include <cuda_runtime.h>
#include <cuda_bf16.h>
#include <cuda_fp16.h>
#include <math.h>
#include <stdint.h>

#define BB   2
#define SS   2048
#define HIDD 2048
#define NH   16
#define HD   128
#define NKV  4
#define MR   (BB*SS)          // 4096
#define KVD  (NKV*HD)         // 512

// -------- scratch (device globals; no allocation allowed) --------
__device__ float g_tmpq[MR * HIDD];
__device__ float g_tmpk[MR * KVD];
__device__ float g_tmpv[MR * KVD];
__device__ float g_q[BB * NH * SS * HD];
__device__ float g_k[BB * NKV * SS * HD];
__device__ float g_v[BB * NKV * SS * HD];
__device__ float g_ctx[MR * HIDD];
__device__ __half g_Af[MR * HIDD];        // A as fp16
__device__ __half g_Wf[HIDD * HIDD];      // W^T as fp16 [N,K]

// ================= helpers =================
__device__ __forceinline__ uint32_t smem_u32(const void* p) {
    uint32_t a;
    asm("{ .reg .u64 t; cvta.to.shared.u64 t, %1; cvt.u32.u64 %0, t; }"
        : "=r"(a) : "l"(p));
    return a;
}

#define CP_ASYNC16(smem, gptr) \
    asm volatile("cp.async.cg.shared.global [%0], [%1], 16;" \
        :: "r"(smem), "l"(gptr))
#define CP_COMMIT() asm volatile("cp.async.commit_group;" ::: "memory")
#define CP_WAIT(n)  asm volatile("cp.async.wait_group %0;" :: "n"(n) : "memory")

#define LDSM4(r0, r1, r2, r3, addr) \
    asm volatile("ldmatrix.sync.aligned.m8n8.x4.shared.b16 {%0,%1,%2,%3}, [%4];" \
        : "=r"(r0), "=r"(r1), "=r"(r2), "=r"(r3) : "r"(addr))

#define MMAF16(c, a, b) \
    asm volatile("mma.sync.aligned.m16n8k16.row.col.f32.f16.f16.f32 " \
        "{%0,%1,%2,%3},{%4,%5,%6,%7},{%8,%9},{%0,%1,%2,%3};" \
        : "+f"((c)[0]), "+f"((c)[1]), "+f"((c)[2]), "+f"((c)[3]) \
        : "r"((a)[0]), "r"((a)[1]), "r"((a)[2]), "r"((a)[3]), \
          "r"((b)[0]), "r"((b)[1]))

// ============================================================
// fp16 conversion kernels
// ============================================================
__global__ __launch_bounds__(256) void aconv(const float* __restrict__ A,
                                             __half* __restrict__ O)
{
    size_t i = ((size_t)blockIdx.x * 256 + threadIdx.x) * 4;
    float4 v = *(const float4*)(A + i);
    union { __half2 h[2]; uint2 u; } H;
    H.h[0] = __floats2half2_rn(v.x, v.y);
    H.h[1] = __floats2half2_rn(v.z, v.w);
    *(uint2*)(O + i) = H.u;
}

// W [Kd,Nd] fp32 -> Wt [Nd,Kd] fp16
__global__ __launch_bounds__(256) void wconv(const float* __restrict__ W,
                                             __half* __restrict__ O,
                                             int Kd, int Nd)
{
    __shared__ float s[32][33];
    int k0 = blockIdx.y * 32, n0 = blockIdx.x * 32;
    int r = threadIdx.x >> 5, c = threadIdx.x & 31;
    #pragma unroll
    for (int j = 0; j < 4; j++)
        s[r + 8 * j][c] = W[(size_t)(k0 + r + 8 * j) * Nd + n0 + c];
    __syncthreads();
    #pragma unroll
    for (int j = 0; j < 4; j++)
        O[(size_t)(n0 + r + 8 * j) * Kd + k0 + c] = __float2half(s[c][r + 8 * j]);
}

// ============================================================
// fp16 mma.sync GEMM: C[M,N] = A[M,K] @ (Wt[N,K])^T + bias
// BM=BN=128, BK=64, 256 threads (8 warps, 4x2 grid, 32x64 warp tile).
// 3-stage cp.async pipeline, XOR-swizzled 128B rows (conflict-free).
// K fixed = HIDD = 2048.
// ============================================================
#define GBK      64
#define NCH      (HIDD / GBK)        // 32
#define TILE_B   16384               // 128 rows x 128 bytes (64 fp16)
#define STAGE_B  (2 * TILE_B)        // A + B = 32768
#define NSTAGE   3
#define GEMM_SMEM (NSTAGE * STAGE_B) // 98304

__global__ __launch_bounds__(256)
void gemm_f16(const __half* __restrict__ A,
              const __half* __restrict__ B,
              const float* __restrict__ bias,
              float* __restrict__ C, int N)
{
    extern __shared__ char smem[];
    const uint32_t smem_base = smem_u32(smem);

    const int tid  = threadIdx.x;
    const int lane = tid & 31;
    const int warp = tid >> 5;
    const int bm = blockIdx.y * 128;
    const int bn = blockIdx.x * 128;

    const int m0 = (warp >> 1) * 32;
    const int n0 = (warp & 1) * 64;

    float acc[2][8][4];
    #pragma unroll
    for (int mt = 0; mt < 2; mt++)
        #pragma unroll
        for (int nf = 0; nf < 8; nf++)
            #pragma unroll
            for (int q = 0; q < 4; q++) acc[mt][nf][q] = 0.f;

    // ldmatrix lane mapping (verified correct in R6 at rel_err 2.2e-5)
    const int a_row = m0 + (lane & 15);
    const int a_c8  = (lane >> 4);            // k 16B-half selector
    const int b_row = n0 + (lane & 7) + ((lane >> 4) << 3);
    const int b_c8  = (lane >> 3) & 1;

    // global->smem: 128 rows x 8 chunks(16B) per tile; 4 iters x 2 tiles
    auto load_stage = [&](int s, int k0) {
        uint32_t sb = smem_base + s * STAGE_B;
        #pragma unroll
        for (int t = 0; t < 4; t++) {
            int cc = tid + 256 * t;
            int r = cc >> 3, c = cc & 7;
            uint32_t off = (uint32_t)(r * 128 + ((c ^ (r & 7)) << 4));
            CP_ASYNC16(sb + off,
                       A + (size_t)(bm + r) * HIDD + k0 + c * 8);
            CP_ASYNC16(sb + TILE_B + off,
                       B + (size_t)(bn + r) * HIDD + k0 + c * 8);
        }
    };

    load_stage(0, 0);
    CP_COMMIT();
    load_stage(1, GBK);
    CP_COMMIT();

    for (int ch = 0; ch < NCH; ch++) {
        if (ch == NCH - 1) { CP_WAIT(0); } else { CP_WAIT(1); }
        __syncthreads();
        if (ch + 2 < NCH) {
            load_stage((ch + 2) % NSTAGE, (ch + 2) * GBK);
            CP_COMMIT();
        }

        const uint32_t sb = smem_base + (ch % NSTAGE) * STAGE_B;
        #pragma unroll
        for (int kk = 0; kk < 4; kk++) {
            uint32_t a[2][4];
            #pragma unroll
            for (int mt = 0; mt < 2; mt++) {
                int row = a_row + mt * 16;
                int ca = kk * 2 + a_c8;
                uint32_t addr = sb + (uint32_t)(row * 128 + ((ca ^ (row & 7)) << 4));
                LDSM4(a[mt][0], a[mt][1], a[mt][2], a[mt][3], addr);
            }
            #pragma unroll
            for (int nf2 = 0; nf2 < 4; nf2++) {
                int row = b_row + nf2 * 16;
                int cb = kk * 2 + b_c8;
                uint32_t addr = sb + TILE_B
                              + (uint32_t)(row * 128 + ((cb ^ (row & 7)) << 4));
                uint32_t b[2][2];
                LDSM4(b[0][0], b[0][1], b[1][0], b[1][1], addr);
                #pragma unroll
                for (int half = 0; half < 2; half++) {
                    const int nf = nf2 * 2 + half;
                    #pragma unroll
                    for (int mt = 0; mt < 2; mt++)
                        MMAF16(acc[mt][nf], a[mt], b[half]);
                }
            }
        }
        __syncthreads();
    }

    // epilogue: bias + store
    #pragma unroll
    for (int mt = 0; mt < 2; mt++) {
        int grow = bm + m0 + mt * 16 + (lane >> 2);
        #pragma unroll
        for (int nf = 0; nf < 8; nf++) {
            int gcol = bn + n0 + nf * 8 + (lane & 3) * 2;
            float2 bv = *(const float2*)(bias + gcol);
            float2 o0, o1;
            o0.x = acc[mt][nf][0] + bv.x;
            o0.y = acc[mt][nf][1] + bv.y;
            o1.x = acc[mt][nf][2] + bv.x;
            o1.y = acc[mt][nf][3] + bv.y;
            *(float2*)(C + (size_t)grow * N + gcol)       = o0;
            *(float2*)(C + (size_t)(grow + 8) * N + gcol) = o1;
        }
    }
}

// ============================================================
// RoPE + transpose
// ============================================================
template <int NHEADS>
__global__ void rope_transpose(const float* __restrict__ tmp,
                               const float* __restrict__ cs,
                               const float* __restrict__ sn,
                               float* __restrict__ out)
{
    int idx = blockIdx.x * blockDim.x + threadIdx.x;
    const int TOT = BB * SS * NHEADS * (HD / 2);
    if (idx >= TOT) return;
    int p = idx & 63;
    int h = (idx >> 6) % NHEADS;
    int rest = idx / (64 * NHEADS);
    int s = rest % SS;
    int b = rest / SS;

    size_t irow = (size_t)(b * SS + s) * (NHEADS * HD) + h * HD + 2 * p;
    float xe = tmp[irow];
    float xo = tmp[irow + 1];
    float c = cs[s * 64 + p];
    float si = sn[s * 64 + p];
    float re = xe * c - xo * si;
    float im = xe * si + xo * c;
    size_t o = ((size_t)(b * NHEADS + h) * SS + s) * HD + 2 * p;
    out[o] = re;
    out[o + 1] = im;
}

__global__ void transpose_v(const float* __restrict__ tmp, float* __restrict__ out)
{
    int idx = blockIdx.x * blockDim.x + threadIdx.x;
    if (idx >= BB * SS * NKV * HD) return;
    int d = idx & 127;
    int h = (idx >> 7) & 3;
    int s = (idx >> 9) & 2047;
    int b = idx >> 20;
    out[((size_t)(b * NKV + h) * SS + s) * HD + d] =
        tmp[(size_t)(b * SS + s) * KVD + h * HD + d];
}

// ============================================================
// Flash-style causal attention (fp32, known-good)
// ============================================================
#define QT 64
#define KT 64
#define DP 132
#define SP 68
#define ATT_SMEM_FLOATS (3*QT*DP + QT*SP + 3*QT)
#define ATT_SMEM_BYTES  (ATT_SMEM_FLOATS*4)

__global__ __launch_bounds__(256, 1) void attn_kernel(
    const float* __restrict__ Qg, const float* __restrict__ Kg,
    const float* __restrict__ Vg, float* __restrict__ ctx)
{
    extern __shared__ float sm[];
    float* Qs   = sm;
    float* Ks   = Qs + QT * DP;
    float* Vs   = Ks + KT * DP;
    float* Ssm  = Vs + KT * DP;
    float* m_sh = Ssm + QT * SP;
    float* l_sh = m_sh + QT;
    float* a_sh = l_sh + QT;

    const int tid = threadIdx.x;
    const int qb = blockIdx.x;
    const int h  = blockIdx.y;
    const int b  = blockIdx.z;
    const int kvh = h >> 2;

    const float* Qbase = Qg + ((size_t)(b * NH + h) * SS + qb * QT) * HD;
    const float* Kbase = Kg + ((size_t)(b * NKV + kvh) * SS) * HD;
    const float* Vbase = Vg + ((size_t)(b * NKV + kvh) * SS) * HD;

    #pragma unroll
    for (int it = 0; it < 8; it++) {
        int lin = tid + it * 256;
        int row = lin >> 5;
        int d4  = (lin & 31) * 4;
        *(float4*)&Qs[row * DP + d4] = *(const float4*)(Qbase + row * HD + d4);
    }
    if (tid < QT) { m_sh[tid] = -1e30f; l_sh[tid] = 0.f; }

    const int warp  = tid >> 5;
    const int warpR = warp >> 1;
    const int warpC = warp & 1;
    const int lr = (tid & 31) >> 3;
    const int lc = tid & 7;
    const int qr0 = warpR * 16 + lr;
    const int kc0 = warpC * 32 + lc;

    const int tr = tid >> 4;
    const int tc = tid & 15;

    float o[4][8];
    #pragma unroll
    for (int i = 0; i < 4; i++)
        #pragma unroll
        for (int j = 0; j < 8; j++) o[i][j] = 0.f;

    const float scale = 0.08838834764831845f;
    const int nkb = qb + 1;

    for (int kb = 0; kb < nkb; kb++) {
        __syncthreads();
        #pragma unroll
        for (int it = 0; it < 8; it++) {
            int lin = tid + it * 256;
            int row = lin >> 5;
            int d4  = (lin & 31) * 4;
            *(float4*)&Ks[row * DP + d4] =
                *(const float4*)(Kbase + (size_t)(kb * KT + row) * HD + d4);
        }
        __syncthreads();

        float acc[4][4];
        #pragma unroll
        for (int i = 0; i < 4; i++)
            #pragma unroll
            for (int j = 0; j < 4; j++) acc[i][j] = 0.f;

        #pragma unroll 8
        for (int d0 = 0; d0 < HD; d0 += 4) {
            float4 qf[4], kf[4];
            #pragma unroll
            for (int i = 0; i < 4; i++)
                qf[i] = *(const float4*)&Qs[(qr0 + 4 * i) * DP + d0];
            #pragma unroll
            for (int j = 0; j < 4; j++)
                kf[j] = *(const float4*)&Ks[(kc0 + 8 * j) * DP + d0];
            #pragma unroll
            for (int i = 0; i < 4; i++)
                #pragma unroll
                for (int j = 0; j < 4; j++)
                    acc[i][j] += qf[i].x * kf[j].x + qf[i].y * kf[j].y
                               + qf[i].z * kf[j].z + qf[i].w * kf[j].w;
        }
        #pragma unroll
        for (int i = 0; i < 4; i++) {
            int qg = qb * QT + qr0 + 4 * i;
            #pragma unroll
            for (int j = 0; j < 4; j++) {
                int kg = kb * KT + kc0 + 8 * j;
                float v = acc[i][j] * scale;
                if (kg > qg) v = -1e30f;
                Ssm[(qr0 + 4 * i) * SP + kc0 + 8 * j] = v;
            }
        }
        __syncthreads();

        #pragma unroll
        for (int it = 0; it < 8; it++) {
            int lin = tid + it * 256;
            int row = lin >> 5;
            int d4  = (lin & 31) * 4;
            *(float4*)&Vs[row * DP + d4] =
                *(const float4*)(Vbase + (size_t)(kb * KT + row) * HD + d4);
        }

        {
            int r  = tid >> 2;
            int c0 = (tid & 3) * 16;
            float mloc = -1e30f;
            #pragma unroll
            for (int c = 0; c < 16; c++) mloc = fmaxf(mloc, Ssm[r * SP + c0 + c]);
            mloc = fmaxf(mloc, __shfl_xor_sync(0xffffffffu, mloc, 1));
            mloc = fmaxf(mloc, __shfl_xor_sync(0xffffffffu, mloc, 2));
            float mold = m_sh[r];
            float mnew = fmaxf(mold, mloc);
            float sum = 0.f;
            #pragma unroll
            for (int c = 0; c < 16; c++) {
                float p = __expf(Ssm[r * SP + c0 + c] - mnew);
                Ssm[r * SP + c0 + c] = p;
                sum += p;
            }
            sum += __shfl_xor_sync(0xffffffffu, sum, 1);
            sum += __shfl_xor_sync(0xffffffffu, sum, 2);
            if ((tid & 3) == 0) {
                float alpha = __expf(mold - mnew);
                l_sh[r] = l_sh[r] * alpha + sum;
                m_sh[r] = mnew;
                a_sh[r] = alpha;
            }
        }
        __syncthreads();

        float al4[4];
        #pragma unroll
        for (int i = 0; i < 4; i++) al4[i] = a_sh[tr * 4 + i];
        #pragma unroll
        for (int i = 0; i < 4; i++)
            #pragma unroll
            for (int j = 0; j < 8; j++) o[i][j] *= al4[i];

        #pragma unroll 4
        for (int kk = 0; kk < KT; kk++) {
            float pv[4];
            #pragma unroll
            for (int i = 0; i < 4; i++) pv[i] = Ssm[(tr * 4 + i) * SP + kk];
            float vv[8];
            #pragma unroll
            for (int j = 0; j < 8; j++) vv[j] = Vs[kk * DP + tc + 16 * j];
            #pragma unroll
            for (int i = 0; i < 4; i++)
                #pragma unroll
                for (int j = 0; j < 8; j++)
                    o[i][j] += pv[i] * vv[j];
        }
    }
    __syncthreads();

    #pragma unroll
    for (int i = 0; i < 4; i++) {
        int srow = qb * QT + tr * 4 + i;
        float inv = 1.f / l_sh[tr * 4 + i];
        size_t base = (size_t)(b * SS + srow) * HIDD + h * HD + tc;
        #pragma unroll
        for (int j = 0; j < 8; j++)
            ctx[base + 16 * j] = o[i][j] * inv;
    }
}

// ============================================================
// launch
// ============================================================
extern "C" void kernel_launch(void* const* d_in, const int* in_sizes, int n_in,
                              void* d_out, int out_size)
{
    const float* query = (const float*)d_in[0];
    const float* key   = (const float*)d_in[1];
    const float* value = (const float*)d_in[2];
    const float* fcos  = (const float*)d_in[4];
    const float* fsin  = (const float*)d_in[5];
    const float* Wq = (const float*)d_in[6];
    const float* bq = (const float*)d_in[7];
    const float* Wk = (const float*)d_in[8];
    const float* bk = (const float*)d_in[9];
    const float* Wv = (const float*)d_in[10];
    const float* bv = (const float*)d_in[11];
    const float* Wo = (const float*)d_in[12];
    const float* bo = (const float*)d_in[13];
    float* out = (float*)d_out;

    float *tmpq, *tmpk, *tmpv, *qT, *kT, *vT, *ctx;
    __half *Af, *Wf;
    cudaGetSymbolAddress((void**)&tmpq, g_tmpq);
    cudaGetSymbolAddress((void**)&tmpk, g_tmpk);
    cudaGetSymbolAddress((void**)&tmpv, g_tmpv);
    cudaGetSymbolAddress((void**)&qT,   g_q);
    cudaGetSymbolAddress((void**)&kT,   g_k);
    cudaGetSymbolAddress((void**)&vT,   g_v);
    cudaGetSymbolAddress((void**)&ctx,  g_ctx);
    cudaGetSymbolAddress((void**)&Af,   g_Af);
    cudaGetSymbolAddress((void**)&Wf,   g_Wf);

    cudaFuncSetAttribute(gemm_f16,
                         cudaFuncAttributeMaxDynamicSharedMemorySize, GEMM_SMEM);
    cudaFuncSetAttribute(attn_kernel,
                         cudaFuncAttributeMaxDynamicSharedMemorySize, ATT_SMEM_BYTES);

    const int ACONV_BLKS = (MR * HIDD) / 1024;   // 8192

    // ---- Q projection ----
    aconv<<<ACONV_BLKS, 256>>>(query, Af);
    wconv<<<dim3(HIDD / 32, HIDD / 32), 256>>>(Wq, Wf, HIDD, HIDD);
    gemm_f16<<<dim3(HIDD / 128, MR / 128), 256, GEMM_SMEM>>>(Af, Wf, bq, tmpq, HIDD);

    // ---- K projection ----
    aconv<<<ACONV_BLKS, 256>>>(key, Af);
    wconv<<<dim3(KVD / 32, HIDD / 32), 256>>>(Wk, Wf, HIDD, KVD);
    gemm_f16<<<dim3(KVD / 128, MR / 128), 256, GEMM_SMEM>>>(Af, Wf, bk, tmpk, KVD);

    // ---- V projection ----
    aconv<<<ACONV_BLKS, 256>>>(value, Af);
    wconv<<<dim3(KVD / 32, HIDD / 32), 256>>>(Wv, Wf, HIDD, KVD);
    gemm_f16<<<dim3(KVD / 128, MR / 128), 256, GEMM_SMEM>>>(Af, Wf, bv, tmpv, KVD);

    // ---- RoPE / transposes ----
    rope_transpose<NH><<<(BB * SS * NH * 64) / 256, 256>>>(tmpq, fcos, fsin, qT);
    rope_transpose<NKV><<<(BB * SS * NKV * 64) / 256, 256>>>(tmpk, fcos, fsin, kT);
    transpose_v<<<(BB * SS * NKV * HD) / 256, 256>>>(tmpv, vT);

    // ---- attention ----
    attn_kernel<<<dim3(SS / QT, NH, BB), 256, ATT_SMEM_BYTES>>>(qT, kT, vT, ctx);

    // ---- O projection ----
    aconv<<<ACONV_BLKS, 256>>>(ctx, Af);
    wconv<<<dim3(HIDD / 32, HIDD / 32), 256>>>(Wo, Wf, HIDD, HIDD);
    gemm_f16<<<dim3(HIDD / 128, MR / 128), 256, GEMM_SMEM>>>(Af, Wf, bo, out, HIDD);
}

// round 11
// speedup vs baseline: 7.7180x; 3.3022x over previous
#include <cuda_runtime.h>
#include <cuda_bf16.h>
#include <cuda_fp16.h>
#include <math.h>
#include <stdint.h>
#include <string.h>

#define BB   2
#define SS   2048
#define HIDD 2048
#define NH   16
#define HD   128
#define NKV  4
#define MR   (BB*SS)          // 4096
#define KVD  (NKV*HD)         // 512

// -------- scratch (device globals; no allocation allowed) --------
__device__ float g_tmpq[MR * HIDD];
__device__ float g_tmpk[MR * KVD];
__device__ float g_tmpv[MR * KVD];
__device__ float g_ctx[MR * HIDD];
__device__ __half g_Af[MR * HIDD];          // A as fp16 (proj input)
__device__ __half g_Wf[HIDD * HIDD];        // W^T as fp16 [N,K]
__device__ __half g_qh[BB * NH * SS * HD];  // roped Q fp16 (pre-scaled)
__device__ __half g_kh[BB * NKV * SS * HD]; // roped K fp16
__device__ __half g_vh[BB * NKV * SS * HD]; // V fp16 [b,kv,s,d]

// ================= helpers =================
__device__ __forceinline__ uint32_t smem_u32(const void* p) {
    uint32_t a;
    asm("{ .reg .u64 t; cvta.to.shared.u64 t, %1; cvt.u32.u64 %0, t; }"
        : "=r"(a) : "l"(p));
    return a;
}

#define CP_ASYNC16(smem, gptr) \
    asm volatile("cp.async.cg.shared.global [%0], [%1], 16;" \
        :: "r"(smem), "l"(gptr))
#define CP_COMMIT() asm volatile("cp.async.commit_group;" ::: "memory")
#define CP_WAIT(n)  asm volatile("cp.async.wait_group %0;" :: "n"(n) : "memory")

#define LDSM4(r0, r1, r2, r3, addr) \
    asm volatile("ldmatrix.sync.aligned.m8n8.x4.shared.b16 {%0,%1,%2,%3}, [%4];" \
        : "=r"(r0), "=r"(r1), "=r"(r2), "=r"(r3) : "r"(addr))

#define LDSM4T(r0, r1, r2, r3, addr) \
    asm volatile("ldmatrix.sync.aligned.m8n8.x4.trans.shared.b16 {%0,%1,%2,%3}, [%4];" \
        : "=r"(r0), "=r"(r1), "=r"(r2), "=r"(r3) : "r"(addr))

#define MMAF16(c, a, b) \
    asm volatile("mma.sync.aligned.m16n8k16.row.col.f32.f16.f16.f32 " \
        "{%0,%1,%2,%3},{%4,%5,%6,%7},{%8,%9},{%0,%1,%2,%3};" \
        : "+f"((c)[0]), "+f"((c)[1]), "+f"((c)[2]), "+f"((c)[3]) \
        : "r"((a)[0]), "r"((a)[1]), "r"((a)[2]), "r"((a)[3]), \
          "r"((b)[0]), "r"((b)[1]))

__device__ __forceinline__ uint32_t pack2(float x, float y) {
    __half2 h = __floats2half2_rn(x, y);
    uint32_t u;
    memcpy(&u, &h, 4);
    return u;
}

// ============================================================
// fp16 conversion kernels
// ============================================================
__global__ __launch_bounds__(256) void aconv(const float* __restrict__ A,
                                             __half* __restrict__ O)
{
    size_t i = ((size_t)blockIdx.x * 256 + threadIdx.x) * 4;
    float4 v = *(const float4*)(A + i);
    union { __half2 h[2]; uint2 u; } H;
    H.h[0] = __floats2half2_rn(v.x, v.y);
    H.h[1] = __floats2half2_rn(v.z, v.w);
    *(uint2*)(O + i) = H.u;
}

// W [Kd,Nd] fp32 -> Wt [Nd,Kd] fp16
__global__ __launch_bounds__(256) void wconv(const float* __restrict__ W,
                                             __half* __restrict__ O,
                                             int Kd, int Nd)
{
    __shared__ float s[32][33];
    int k0 = blockIdx.y * 32, n0 = blockIdx.x * 32;
    int r = threadIdx.x >> 5, c = threadIdx.x & 31;
    #pragma unroll
    for (int j = 0; j < 4; j++)
        s[r + 8 * j][c] = W[(size_t)(k0 + r + 8 * j) * Nd + n0 + c];
    __syncthreads();
    #pragma unroll
    for (int j = 0; j < 4; j++)
        O[(size_t)(n0 + r + 8 * j) * Kd + k0 + c] = __float2half(s[c][r + 8 * j]);
}

// ============================================================
// fp16 mma.sync GEMM (unchanged from R9, validated)
// ============================================================
#define GBK      64
#define NCH      (HIDD / GBK)        // 32
#define TILE_B   16384
#define STAGE_B  (2 * TILE_B)
#define NSTAGE   3
#define GEMM_SMEM (NSTAGE * STAGE_B) // 98304

__global__ __launch_bounds__(256)
void gemm_f16(const __half* __restrict__ A,
              const __half* __restrict__ B,
              const float* __restrict__ bias,
              float* __restrict__ C, int N)
{
    extern __shared__ char smem[];
    const uint32_t smem_base = smem_u32(smem);

    const int tid  = threadIdx.x;
    const int lane = tid & 31;
    const int warp = tid >> 5;
    const int bm = blockIdx.y * 128;
    const int bn = blockIdx.x * 128;

    const int m0 = (warp >> 1) * 32;
    const int n0 = (warp & 1) * 64;

    float acc[2][8][4];
    #pragma unroll
    for (int mt = 0; mt < 2; mt++)
        #pragma unroll
        for (int nf = 0; nf < 8; nf++)
            #pragma unroll
            for (int q = 0; q < 4; q++) acc[mt][nf][q] = 0.f;

    const int a_row = m0 + (lane & 15);
    const int a_c8  = (lane >> 4);
    const int b_row = n0 + (lane & 7) + ((lane >> 4) << 3);
    const int b_c8  = (lane >> 3) & 1;

    auto load_stage = [&](int s, int k0) {
        uint32_t sb = smem_base + s * STAGE_B;
        #pragma unroll
        for (int t = 0; t < 4; t++) {
            int cc = tid + 256 * t;
            int r = cc >> 3, c = cc & 7;
            uint32_t off = (uint32_t)(r * 128 + ((c ^ (r & 7)) << 4));
            CP_ASYNC16(sb + off,
                       A + (size_t)(bm + r) * HIDD + k0 + c * 8);
            CP_ASYNC16(sb + TILE_B + off,
                       B + (size_t)(bn + r) * HIDD + k0 + c * 8);
        }
    };

    load_stage(0, 0);
    CP_COMMIT();
    load_stage(1, GBK);
    CP_COMMIT();

    for (int ch = 0; ch < NCH; ch++) {
        if (ch == NCH - 1) { CP_WAIT(0); } else { CP_WAIT(1); }
        __syncthreads();
        if (ch + 2 < NCH) {
            load_stage((ch + 2) % NSTAGE, (ch + 2) * GBK);
            CP_COMMIT();
        }

        const uint32_t sb = smem_base + (ch % NSTAGE) * STAGE_B;
        #pragma unroll
        for (int kk = 0; kk < 4; kk++) {
            uint32_t a[2][4];
            #pragma unroll
            for (int mt = 0; mt < 2; mt++) {
                int row = a_row + mt * 16;
                int ca = kk * 2 + a_c8;
                uint32_t addr = sb + (uint32_t)(row * 128 + ((ca ^ (row & 7)) << 4));
                LDSM4(a[mt][0], a[mt][1], a[mt][2], a[mt][3], addr);
            }
            #pragma unroll
            for (int nf2 = 0; nf2 < 4; nf2++) {
                int row = b_row + nf2 * 16;
                int cb = kk * 2 + b_c8;
                uint32_t addr = sb + TILE_B
                              + (uint32_t)(row * 128 + ((cb ^ (row & 7)) << 4));
                uint32_t b[2][2];
                LDSM4(b[0][0], b[0][1], b[1][0], b[1][1], addr);
                #pragma unroll
                for (int half = 0; half < 2; half++) {
                    const int nf = nf2 * 2 + half;
                    #pragma unroll
                    for (int mt = 0; mt < 2; mt++)
                        MMAF16(acc[mt][nf], a[mt], b[half]);
                }
            }
        }
        __syncthreads();
    }

    #pragma unroll
    for (int mt = 0; mt < 2; mt++) {
        int grow = bm + m0 + mt * 16 + (lane >> 2);
        #pragma unroll
        for (int nf = 0; nf < 8; nf++) {
            int gcol = bn + n0 + nf * 8 + (lane & 3) * 2;
            float2 bv = *(const float2*)(bias + gcol);
            float2 o0, o1;
            o0.x = acc[mt][nf][0] + bv.x;
            o0.y = acc[mt][nf][1] + bv.y;
            o1.x = acc[mt][nf][2] + bv.x;
            o1.y = acc[mt][nf][3] + bv.y;
            *(float2*)(C + (size_t)grow * N + gcol)       = o0;
            *(float2*)(C + (size_t)(grow + 8) * N + gcol) = o1;
        }
    }
}

// ============================================================
// RoPE -> fp16 [b,head,s,d]; Q pre-scaled by 1/sqrt(D)
// ============================================================
template <int NHEADS>
__global__ void rope_f16(const float* __restrict__ tmp,
                         const float* __restrict__ cs,
                         const float* __restrict__ sn,
                         __half* __restrict__ out, float scale)
{
    int idx = blockIdx.x * blockDim.x + threadIdx.x;
    const int TOT = BB * SS * NHEADS * (HD / 2);
    if (idx >= TOT) return;
    int p = idx & 63;
    int h = (idx >> 6) % NHEADS;
    int rest = idx / (64 * NHEADS);
    int s = rest % SS;
    int b = rest / SS;

    size_t irow = (size_t)(b * SS + s) * (NHEADS * HD) + h * HD + 2 * p;
    float xe = tmp[irow];
    float xo = tmp[irow + 1];
    float c = cs[s * 64 + p];
    float si = sn[s * 64 + p];
    float re = (xe * c - xo * si) * scale;
    float im = (xe * si + xo * c) * scale;
    size_t o = ((size_t)(b * NHEADS + h) * SS + s) * HD + 2 * p;
    *(__half2*)(out + o) = __floats2half2_rn(re, im);
}

__global__ void transpose_v_f16(const float* __restrict__ tmp,
                                __half* __restrict__ out)
{
    int idx = blockIdx.x * blockDim.x + threadIdx.x;
    if (idx >= BB * SS * NKV * HD) return;
    int d = idx & 127;
    int h = (idx >> 7) & 3;
    int s = (idx >> 9) & 2047;
    int b = idx >> 20;
    out[((size_t)(b * NKV + h) * SS + s) * HD + d] =
        __float2half(tmp[(size_t)(b * SS + s) * KVD + h * HD + d]);
}

// ============================================================
// fp16 mma flash attention. 128x128 tiles, 8 warps x 16 rows.
// Q frags persistent in regs; P stays in regs (FA2); V via ldmatrix.trans.
// smem: Q 32K | (K+V) x 2 stages 64K each = 160 KB.
// ============================================================
#define ATT_SMEM (5 * 32768)
// swizzled 16B-chunk offset in a 128-row x 256B tile
#define SWZ(r, c) ((uint32_t)((r) * 256 + (((((c) ^ (r)) & 7) | ((c) & 8)) << 4)))

__global__ __launch_bounds__(256, 1)
void attn_f16(const __half* __restrict__ Qg, const __half* __restrict__ Kg,
              const __half* __restrict__ Vg, float* __restrict__ ctx)
{
    extern __shared__ char smem[];
    const uint32_t sb = smem_u32(smem);
    const uint32_t Qs = sb;

    const int tid  = threadIdx.x;
    const int lane = tid & 31;
    const int warp = tid >> 5;
    const int qb = (int)gridDim.x - 1 - (int)blockIdx.x;  // big blocks first
    const int h = blockIdx.y, b = blockIdx.z;
    const int kvh = h >> 2;

    const __half* Qbase = Qg + ((size_t)(b * NH + h) * SS + qb * 128) * HD;
    const __half* Kbase = Kg + ((size_t)(b * NKV + kvh) * SS) * HD;
    const __half* Vbase = Vg + ((size_t)(b * NKV + kvh) * SS) * HD;

    // ---- load Q tile ----
    #pragma unroll
    for (int it = 0; it < 8; it++) {
        int lin = tid + 256 * it;
        int r = lin >> 4, c = lin & 15;
        CP_ASYNC16(Qs + SWZ(r, c), Qbase + r * HD + c * 8);
    }
    CP_COMMIT();

    auto load_kv = [&](int s, int k0) {
        uint32_t Kt = sb + 32768 + s * 65536;
        #pragma unroll
        for (int it = 0; it < 8; it++) {
            int lin = tid + 256 * it;
            int r = lin >> 4, c = lin & 15;
            uint32_t off = SWZ(r, c);
            CP_ASYNC16(Kt + off,         Kbase + (size_t)(k0 + r) * HD + c * 8);
            CP_ASYNC16(Kt + 32768 + off, Vbase + (size_t)(k0 + r) * HD + c * 8);
        }
    };
    load_kv(0, 0);
    CP_COMMIT();
    CP_WAIT(0);
    __syncthreads();

    // ---- persistent Q fragments ----
    uint32_t qa[8][4];
    {
        int ar = warp * 16 + (lane & 15);
        int ahi = lane >> 4;
        #pragma unroll
        for (int kk = 0; kk < 8; kk++) {
            uint32_t addr = Qs + SWZ(ar, kk * 2 + ahi);
            LDSM4(qa[kk][0], qa[kk][1], qa[kk][2], qa[kk][3], addr);
        }
    }

    float oacc[16][4];
    #pragma unroll
    for (int nf = 0; nf < 16; nf++)
        #pragma unroll
        for (int q = 0; q < 4; q++) oacc[nf][q] = 0.f;

    float m0 = -1e30f, m1 = -1e30f, l0 = 0.f, l1 = 0.f;
    const int row0 = lane >> 2;                     // 0..7; lane rows = row0, row0+8

    const int kb_row = (lane & 7) + ((lane >> 4) << 3);     // K (non-trans B)
    const int kb_c   = (lane >> 3) & 1;
    const int vb_row = (lane & 7) + (((lane >> 3) & 1) << 3); // V (trans B)
    const int vb_c   = lane >> 4;

    const int ntiles = qb + 1;
    for (int t = 0; t < ntiles; t++) {
        if (t + 1 < ntiles) {
            load_kv((t + 1) & 1, (t + 1) * 128);
            CP_COMMIT();
            CP_WAIT(1);
        } else {
            CP_WAIT(0);
        }
        __syncthreads();
        const uint32_t Kt = sb + 32768 + (t & 1) * 65536;
        const uint32_t Vt = Kt + 32768;

        // ---- S = Q @ K^T ----
        float sacc[16][4];
        #pragma unroll
        for (int nf = 0; nf < 16; nf++)
            #pragma unroll
            for (int q = 0; q < 4; q++) sacc[nf][q] = 0.f;

        #pragma unroll
        for (int kk = 0; kk < 8; kk++) {
            #pragma unroll
            for (int nf2 = 0; nf2 < 8; nf2++) {
                uint32_t bk[4];
                uint32_t addr = Kt + SWZ(nf2 * 16 + kb_row, kk * 2 + kb_c);
                LDSM4(bk[0], bk[1], bk[2], bk[3], addr);
                MMAF16(sacc[nf2 * 2],     qa[kk], bk);
                MMAF16(sacc[nf2 * 2 + 1], qa[kk], bk + 2);
            }
        }

        // ---- causal mask (diagonal tile only) ----
        if (t == qb) {
            int qg = warp * 16 + row0;
            #pragma unroll
            for (int nf = 0; nf < 16; nf++) {
                int kg = nf * 8 + (lane & 3) * 2;
                if (kg > qg)         sacc[nf][0] = -1e30f;
                if (kg + 1 > qg)     sacc[nf][1] = -1e30f;
                if (kg > qg + 8)     sacc[nf][2] = -1e30f;
                if (kg + 1 > qg + 8) sacc[nf][3] = -1e30f;
            }
        }

        // ---- online softmax (in registers) ----
        float mx0 = -1e30f, mx1 = -1e30f;
        #pragma unroll
        for (int nf = 0; nf < 16; nf++) {
            mx0 = fmaxf(mx0, fmaxf(sacc[nf][0], sacc[nf][1]));
            mx1 = fmaxf(mx1, fmaxf(sacc[nf][2], sacc[nf][3]));
        }
        mx0 = fmaxf(mx0, __shfl_xor_sync(0xffffffffu, mx0, 1));
        mx0 = fmaxf(mx0, __shfl_xor_sync(0xffffffffu, mx0, 2));
        mx1 = fmaxf(mx1, __shfl_xor_sync(0xffffffffu, mx1, 1));
        mx1 = fmaxf(mx1, __shfl_xor_sync(0xffffffffu, mx1, 2));
        float mn0 = fmaxf(m0, mx0), mn1 = fmaxf(m1, mx1);
        float al0 = __expf(m0 - mn0), al1 = __expf(m1 - mn1);
        m0 = mn0; m1 = mn1;
        float s0 = 0.f, s1 = 0.f;
        #pragma unroll
        for (int nf = 0; nf < 16; nf++) {
            sacc[nf][0] = __expf(sacc[nf][0] - mn0); s0 += sacc[nf][0];
            sacc[nf][1] = __expf(sacc[nf][1] - mn0); s0 += sacc[nf][1];
            sacc[nf][2] = __expf(sacc[nf][2] - mn1); s1 += sacc[nf][2];
            sacc[nf][3] = __expf(sacc[nf][3] - mn1); s1 += sacc[nf][3];
        }
        s0 += __shfl_xor_sync(0xffffffffu, s0, 1);
        s0 += __shfl_xor_sync(0xffffffffu, s0, 2);
        s1 += __shfl_xor_sync(0xffffffffu, s1, 1);
        s1 += __shfl_xor_sync(0xffffffffu, s1, 2);
        l0 = l0 * al0 + s0;
        l1 = l1 * al1 + s1;
        #pragma unroll
        for (int nf = 0; nf < 16; nf++) {
            oacc[nf][0] *= al0; oacc[nf][1] *= al0;
            oacc[nf][2] *= al1; oacc[nf][3] *= al1;
        }

        // ---- O += P @ V (P from registers, V via ldmatrix.trans) ----
        #pragma unroll
        for (int kc = 0; kc < 8; kc++) {
            uint32_t pa[4];
            pa[0] = pack2(sacc[2 * kc][0],     sacc[2 * kc][1]);
            pa[1] = pack2(sacc[2 * kc][2],     sacc[2 * kc][3]);
            pa[2] = pack2(sacc[2 * kc + 1][0], sacc[2 * kc + 1][1]);
            pa[3] = pack2(sacc[2 * kc + 1][2], sacc[2 * kc + 1][3]);
            #pragma unroll
            for (int dg2 = 0; dg2 < 8; dg2++) {
                uint32_t bv[4];
                uint32_t addr = Vt + SWZ(kc * 16 + vb_row, dg2 * 2 + vb_c);
                LDSM4T(bv[0], bv[1], bv[2], bv[3], addr);
                MMAF16(oacc[dg2 * 2],     pa, bv);
                MMAF16(oacc[dg2 * 2 + 1], pa, bv + 2);
            }
        }
        __syncthreads();
    }

    // ---- normalize + write ctx ----
    float inv0 = 1.f / l0, inv1 = 1.f / l1;
    int gr = qb * 128 + warp * 16 + row0;
    #pragma unroll
    for (int nf = 0; nf < 16; nf++) {
        int col = h * HD + nf * 8 + (lane & 3) * 2;
        float2 v0 = make_float2(oacc[nf][0] * inv0, oacc[nf][1] * inv0);
        float2 v1 = make_float2(oacc[nf][2] * inv1, oacc[nf][3] * inv1);
        *(float2*)(ctx + (size_t)(b * SS + gr) * HIDD + col)     = v0;
        *(float2*)(ctx + (size_t)(b * SS + gr + 8) * HIDD + col) = v1;
    }
}

// ============================================================
// launch
// ============================================================
extern "C" void kernel_launch(void* const* d_in, const int* in_sizes, int n_in,
                              void* d_out, int out_size)
{
    const float* query = (const float*)d_in[0];
    const float* key   = (const float*)d_in[1];
    const float* value = (const float*)d_in[2];
    const float* fcos  = (const float*)d_in[4];
    const float* fsin  = (const float*)d_in[5];
    const float* Wq = (const float*)d_in[6];
    const float* bq = (const float*)d_in[7];
    const float* Wk = (const float*)d_in[8];
    const float* bk = (const float*)d_in[9];
    const float* Wv = (const float*)d_in[10];
    const float* bv = (const float*)d_in[11];
    const float* Wo = (const float*)d_in[12];
    const float* bo = (const float*)d_in[13];
    float* out = (float*)d_out;

    float *tmpq, *tmpk, *tmpv, *ctx;
    __half *Af, *Wf, *qh, *kh, *vh;
    cudaGetSymbolAddress((void**)&tmpq, g_tmpq);
    cudaGetSymbolAddress((void**)&tmpk, g_tmpk);
    cudaGetSymbolAddress((void**)&tmpv, g_tmpv);
    cudaGetSymbolAddress((void**)&ctx,  g_ctx);
    cudaGetSymbolAddress((void**)&Af,   g_Af);
    cudaGetSymbolAddress((void**)&Wf,   g_Wf);
    cudaGetSymbolAddress((void**)&qh,   g_qh);
    cudaGetSymbolAddress((void**)&kh,   g_kh);
    cudaGetSymbolAddress((void**)&vh,   g_vh);

    cudaFuncSetAttribute(gemm_f16,
                         cudaFuncAttributeMaxDynamicSharedMemorySize, GEMM_SMEM);
    cudaFuncSetAttribute(attn_f16,
                         cudaFuncAttributeMaxDynamicSharedMemorySize, ATT_SMEM);

    const int ACONV_BLKS = (MR * HIDD) / 1024;   // 8192
    const float QSCALE = 0.08838834764831845f;   // 1/sqrt(128)

    // ---- Q projection ----
    aconv<<<ACONV_BLKS, 256>>>(query, Af);
    wconv<<<dim3(HIDD / 32, HIDD / 32), 256>>>(Wq, Wf, HIDD, HIDD);
    gemm_f16<<<dim3(HIDD / 128, MR / 128), 256, GEMM_SMEM>>>(Af, Wf, bq, tmpq, HIDD);

    // ---- K projection ----
    aconv<<<ACONV_BLKS, 256>>>(key, Af);
    wconv<<<dim3(KVD / 32, HIDD / 32), 256>>>(Wk, Wf, HIDD, KVD);
    gemm_f16<<<dim3(KVD / 128, MR / 128), 256, GEMM_SMEM>>>(Af, Wf, bk, tmpk, KVD);

    // ---- V projection ----
    aconv<<<ACONV_BLKS, 256>>>(value, Af);
    wconv<<<dim3(KVD / 32, HIDD / 32), 256>>>(Wv, Wf, HIDD, KVD);
    gemm_f16<<<dim3(KVD / 128, MR / 128), 256, GEMM_SMEM>>>(Af, Wf, bv, tmpv, KVD);

    // ---- RoPE / transposes -> fp16 ----
    rope_f16<NH><<<(BB * SS * NH * 64) / 256, 256>>>(tmpq, fcos, fsin, qh, QSCALE);
    rope_f16<NKV><<<(BB * SS * NKV * 64) / 256, 256>>>(tmpk, fcos, fsin, kh, 1.0f);
    transpose_v_f16<<<(BB * SS * NKV * HD) / 256, 256>>>(tmpv, vh);

    // ---- attention (fp16 mma, FA2-style) ----
    attn_f16<<<dim3(SS / 128, NH, BB), 256, ATT_SMEM>>>(qh, kh, vh, ctx);

    // ---- O projection ----
    aconv<<<ACONV_BLKS, 256>>>(ctx, Af);
    wconv<<<dim3(HIDD / 32, HIDD / 32), 256>>>(Wo, Wf, HIDD, HIDD);
    gemm_f16<<<dim3(HIDD / 128, MR / 128), 256, GEMM_SMEM>>>(Af, Wf, bo, out, HIDD);
}

// round 13
// speedup vs baseline: 7.7652x; 1.0061x over previous
#include <cuda_runtime.h>
#include <cuda_bf16.h>
#include <cuda_fp16.h>
#include <math.h>
#include <stdint.h>
#include <string.h>

#define BB   2
#define SS   2048
#define HIDD 2048
#define NH   16
#define HD   128
#define NKV  4
#define MR   (BB*SS)          // 4096
#define KVD  (NKV*HD)         // 512

// -------- scratch (device globals; no allocation allowed) --------
__device__ __half g_Af[MR * HIDD];          // projection input as fp16
__device__ __half g_Wf[HIDD * HIDD];        // W^T as fp16 [N,K]
__device__ __half g_qh[BB * NH * SS * HD];  // roped Q fp16 (pre-scaled)
__device__ __half g_kh[BB * NKV * SS * HD]; // roped K fp16
__device__ __half g_vh[BB * NKV * SS * HD]; // V fp16 [b,kv,s,d]
__device__ __half g_ctxh[MR * HIDD];        // attention output fp16

// ================= helpers =================
__device__ __forceinline__ uint32_t smem_u32(const void* p) {
    uint32_t a;
    asm("{ .reg .u64 t; cvta.to.shared.u64 t, %1; cvt.u32.u64 %0, t; }"
        : "=r"(a) : "l"(p));
    return a;
}

#define CP_ASYNC16(smem, gptr) \
    asm volatile("cp.async.cg.shared.global [%0], [%1], 16;" \
        :: "r"(smem), "l"(gptr))
#define CP_COMMIT() asm volatile("cp.async.commit_group;" ::: "memory")
#define CP_WAIT(n)  asm volatile("cp.async.wait_group %0;" :: "n"(n) : "memory")

#define LDSM4(r0, r1, r2, r3, addr) \
    asm volatile("ldmatrix.sync.aligned.m8n8.x4.shared.b16 {%0,%1,%2,%3}, [%4];" \
        : "=r"(r0), "=r"(r1), "=r"(r2), "=r"(r3) : "r"(addr))

#define LDSM4T(r0, r1, r2, r3, addr) \
    asm volatile("ldmatrix.sync.aligned.m8n8.x4.trans.shared.b16 {%0,%1,%2,%3}, [%4];" \
        : "=r"(r0), "=r"(r1), "=r"(r2), "=r"(r3) : "r"(addr))

#define MMAF16(c, a, b) \
    asm volatile("mma.sync.aligned.m16n8k16.row.col.f32.f16.f16.f32 " \
        "{%0,%1,%2,%3},{%4,%5,%6,%7},{%8,%9},{%0,%1,%2,%3};" \
        : "+f"((c)[0]), "+f"((c)[1]), "+f"((c)[2]), "+f"((c)[3]) \
        : "r"((a)[0]), "r"((a)[1]), "r"((a)[2]), "r"((a)[3]), \
          "r"((b)[0]), "r"((b)[1]))

__device__ __forceinline__ uint32_t pack2(float x, float y) {
    __half2 h = __floats2half2_rn(x, y);
    uint32_t u;
    memcpy(&u, &h, 4);
    return u;
}

// ============================================================
// fp16 conversion kernels
// ============================================================
__global__ __launch_bounds__(256) void aconv(const float* __restrict__ A,
                                             __half* __restrict__ O)
{
    size_t i = ((size_t)blockIdx.x * 256 + threadIdx.x) * 4;
    float4 v = *(const float4*)(A + i);
    union { __half2 h[2]; uint2 u; } H;
    H.h[0] = __floats2half2_rn(v.x, v.y);
    H.h[1] = __floats2half2_rn(v.z, v.w);
    *(uint2*)(O + i) = H.u;
}

// W [Kd,Nd] fp32 -> Wt [Nd,Kd] fp16
__global__ __launch_bounds__(256) void wconv(const float* __restrict__ W,
                                             __half* __restrict__ O,
                                             int Kd, int Nd)
{
    __shared__ float s[32][33];
    int k0 = blockIdx.y * 32, n0 = blockIdx.x * 32;
    int r = threadIdx.x >> 5, c = threadIdx.x & 31;
    #pragma unroll
    for (int j = 0; j < 4; j++)
        s[r + 8 * j][c] = W[(size_t)(k0 + r + 8 * j) * Nd + n0 + c];
    __syncthreads();
    #pragma unroll
    for (int j = 0; j < 4; j++)
        O[(size_t)(n0 + r + 8 * j) * Kd + k0 + c] = __float2half(s[c][r + 8 * j]);
}

// ============================================================
// fp16 mma.sync GEMM with fused epilogues.
// MODE 0: fp32 out + bias (row-major [M,N])
// MODE 1: bias + RoPE + scale -> fp16 out [b, h, s, d]   (h = col/HD)
// MODE 2: bias -> fp16 out [b, h, s, d]                  (no rotation)
// ============================================================
#define GBK      64
#define NCH      (HIDD / GBK)        // 32
#define TILE_B   16384
#define STAGE_B  (2 * TILE_B)
#define NSTAGE   3
#define GEMM_SMEM (NSTAGE * STAGE_B) // 98304

template <int MODE>
__global__ __launch_bounds__(256)
void gemm_f16(const __half* __restrict__ A,
              const __half* __restrict__ B,
              const float* __restrict__ bias,
              void* __restrict__ Cout,
              const float* __restrict__ cs,
              const float* __restrict__ sn,
              int N, float scale)
{
    extern __shared__ char smem[];
    const uint32_t smem_base = smem_u32(smem);

    const int tid  = threadIdx.x;
    const int lane = tid & 31;
    const int warp = tid >> 5;
    const int bm = blockIdx.y * 128;
    const int bn = blockIdx.x * 128;

    const int m0 = (warp >> 1) * 32;
    const int n0 = (warp & 1) * 64;

    float acc[2][8][4];
    #pragma unroll
    for (int mt = 0; mt < 2; mt++)
        #pragma unroll
        for (int nf = 0; nf < 8; nf++)
            #pragma unroll
            for (int q = 0; q < 4; q++) acc[mt][nf][q] = 0.f;

    const int a_row = m0 + (lane & 15);
    const int a_c8  = (lane >> 4);
    const int b_row = n0 + (lane & 7) + ((lane >> 4) << 3);
    const int b_c8  = (lane >> 3) & 1;

    auto load_stage = [&](int s, int k0) {
        uint32_t sb = smem_base + s * STAGE_B;
        #pragma unroll
        for (int t = 0; t < 4; t++) {
            int cc = tid + 256 * t;
            int r = cc >> 3, c = cc & 7;
            uint32_t off = (uint32_t)(r * 128 + ((c ^ (r & 7)) << 4));
            CP_ASYNC16(sb + off,
                       A + (size_t)(bm + r) * HIDD + k0 + c * 8);
            CP_ASYNC16(sb + TILE_B + off,
                       B + (size_t)(bn + r) * HIDD + k0 + c * 8);
        }
    };

    load_stage(0, 0);
    CP_COMMIT();
    load_stage(1, GBK);
    CP_COMMIT();

    for (int ch = 0; ch < NCH; ch++) {
        if (ch == NCH - 1) { CP_WAIT(0); } else { CP_WAIT(1); }
        __syncthreads();
        if (ch + 2 < NCH) {
            load_stage((ch + 2) % NSTAGE, (ch + 2) * GBK);
            CP_COMMIT();
        }

        const uint32_t sb = smem_base + (ch % NSTAGE) * STAGE_B;
        #pragma unroll
        for (int kk = 0; kk < 4; kk++) {
            uint32_t a[2][4];
            #pragma unroll
            for (int mt = 0; mt < 2; mt++) {
                int row = a_row + mt * 16;
                int ca = kk * 2 + a_c8;
                uint32_t addr = sb + (uint32_t)(row * 128 + ((ca ^ (row & 7)) << 4));
                LDSM4(a[mt][0], a[mt][1], a[mt][2], a[mt][3], addr);
            }
            #pragma unroll
            for (int nf2 = 0; nf2 < 4; nf2++) {
                int row = b_row + nf2 * 16;
                int cb = kk * 2 + b_c8;
                uint32_t addr = sb + TILE_B
                              + (uint32_t)(row * 128 + ((cb ^ (row & 7)) << 4));
                uint32_t b[2][2];
                LDSM4(b[0][0], b[0][1], b[1][0], b[1][1], addr);
                #pragma unroll
                for (int half = 0; half < 2; half++) {
                    const int nf = nf2 * 2 + half;
                    #pragma unroll
                    for (int mt = 0; mt < 2; mt++)
                        MMAF16(acc[mt][nf], a[mt], b[half]);
                }
            }
        }
        __syncthreads();
    }

    // ---- fused epilogue ----
    #pragma unroll
    for (int mt = 0; mt < 2; mt++) {
        int grow0 = bm + m0 + mt * 16 + (lane >> 2);
        #pragma unroll
        for (int nf = 0; nf < 8; nf++) {
            int gcol = bn + n0 + nf * 8 + (lane & 3) * 2;
            float2 bv = *(const float2*)(bias + gcol);
            #pragma unroll
            for (int hf = 0; hf < 2; hf++) {
                int r = grow0 + hf * 8;
                float x0 = acc[mt][nf][hf * 2 + 0] + bv.x;
                float x1 = acc[mt][nf][hf * 2 + 1] + bv.y;
                if (MODE == 0) {
                    *(float2*)((float*)Cout + (size_t)r * N + gcol) =
                        make_float2(x0, x1);
                } else {
                    int bb = r / SS, s = r % SS;
                    int hh = gcol / HD, d = gcol % HD;
                    size_t o = ((size_t)(bb * (N / HD) + hh) * SS + s) * HD + d;
                    if (MODE == 1) {
                        int p = d >> 1;
                        float c  = cs[s * 64 + p];
                        float si = sn[s * 64 + p];
                        float re = (x0 * c - x1 * si) * scale;
                        float im = (x0 * si + x1 * c) * scale;
                        *(__half2*)((__half*)Cout + o) = __floats2half2_rn(re, im);
                    } else {
                        *(__half2*)((__half*)Cout + o) = __floats2half2_rn(x0, x1);
                    }
                }
            }
        }
    }
}

// ============================================================
// fp16 mma flash attention (validated R11) — now writes fp16 ctx.
// ============================================================
#define ATT_SMEM (5 * 32768)
#define SWZ(r, c) ((uint32_t)((r) * 256 + (((((c) ^ (r)) & 7) | ((c) & 8)) << 4)))

__global__ __launch_bounds__(256, 1)
void attn_f16(const __half* __restrict__ Qg, const __half* __restrict__ Kg,
              const __half* __restrict__ Vg, __half* __restrict__ ctx)
{
    extern __shared__ char smem[];
    const uint32_t sb = smem_u32(smem);
    const uint32_t Qs = sb;

    const int tid  = threadIdx.x;
    const int lane = tid & 31;
    const int warp = tid >> 5;
    const int qb = (int)gridDim.x - 1 - (int)blockIdx.x;
    const int h = blockIdx.y, b = blockIdx.z;
    const int kvh = h >> 2;

    const __half* Qbase = Qg + ((size_t)(b * NH + h) * SS + qb * 128) * HD;
    const __half* Kbase = Kg + ((size_t)(b * NKV + kvh) * SS) * HD;
    const __half* Vbase = Vg + ((size_t)(b * NKV + kvh) * SS) * HD;

    #pragma unroll
    for (int it = 0; it < 8; it++) {
        int lin = tid + 256 * it;
        int r = lin >> 4, c = lin & 15;
        CP_ASYNC16(Qs + SWZ(r, c), Qbase + r * HD + c * 8);
    }
    CP_COMMIT();

    auto load_kv = [&](int s, int k0) {
        uint32_t Kt = sb + 32768 + s * 65536;
        #pragma unroll
        for (int it = 0; it < 8; it++) {
            int lin = tid + 256 * it;
            int r = lin >> 4, c = lin & 15;
            uint32_t off = SWZ(r, c);
            CP_ASYNC16(Kt + off,         Kbase + (size_t)(k0 + r) * HD + c * 8);
            CP_ASYNC16(Kt + 32768 + off, Vbase + (size_t)(k0 + r) * HD + c * 8);
        }
    };
    load_kv(0, 0);
    CP_COMMIT();
    CP_WAIT(0);
    __syncthreads();

    uint32_t qa[8][4];
    {
        int ar = warp * 16 + (lane & 15);
        int ahi = lane >> 4;
        #pragma unroll
        for (int kk = 0; kk < 8; kk++) {
            uint32_t addr = Qs + SWZ(ar, kk * 2 + ahi);
            LDSM4(qa[kk][0], qa[kk][1], qa[kk][2], qa[kk][3], addr);
        }
    }

    float oacc[16][4];
    #pragma unroll
    for (int nf = 0; nf < 16; nf++)
        #pragma unroll
        for (int q = 0; q < 4; q++) oacc[nf][q] = 0.f;

    float m0 = -1e30f, m1 = -1e30f, l0 = 0.f, l1 = 0.f;
    const int row0 = lane >> 2;

    const int kb_row = (lane & 7) + ((lane >> 4) << 3);
    const int kb_c   = (lane >> 3) & 1;
    const int vb_row = (lane & 7) + (((lane >> 3) & 1) << 3);
    const int vb_c   = lane >> 4;

    const int ntiles = qb + 1;
    for (int t = 0; t < ntiles; t++) {
        if (t + 1 < ntiles) {
            load_kv((t + 1) & 1, (t + 1) * 128);
            CP_COMMIT();
            CP_WAIT(1);
        } else {
            CP_WAIT(0);
        }
        __syncthreads();
        const uint32_t Kt = sb + 32768 + (t & 1) * 65536;
        const uint32_t Vt = Kt + 32768;

        float sacc[16][4];
        #pragma unroll
        for (int nf = 0; nf < 16; nf++)
            #pragma unroll
            for (int q = 0; q < 4; q++) sacc[nf][q] = 0.f;

        #pragma unroll
        for (int kk = 0; kk < 8; kk++) {
            #pragma unroll
            for (int nf2 = 0; nf2 < 8; nf2++) {
                uint32_t bk[4];
                uint32_t addr = Kt + SWZ(nf2 * 16 + kb_row, kk * 2 + kb_c);
                LDSM4(bk[0], bk[1], bk[2], bk[3], addr);
                MMAF16(sacc[nf2 * 2],     qa[kk], bk);
                MMAF16(sacc[nf2 * 2 + 1], qa[kk], bk + 2);
            }
        }

        if (t == qb) {
            int qg = warp * 16 + row0;
            #pragma unroll
            for (int nf = 0; nf < 16; nf++) {
                int kg = nf * 8 + (lane & 3) * 2;
                if (kg > qg)         sacc[nf][0] = -1e30f;
                if (kg + 1 > qg)     sacc[nf][1] = -1e30f;
                if (kg > qg + 8)     sacc[nf][2] = -1e30f;
                if (kg + 1 > qg + 8) sacc[nf][3] = -1e30f;
            }
        }

        float mx0 = -1e30f, mx1 = -1e30f;
        #pragma unroll
        for (int nf = 0; nf < 16; nf++) {
            mx0 = fmaxf(mx0, fmaxf(sacc[nf][0], sacc[nf][1]));
            mx1 = fmaxf(mx1, fmaxf(sacc[nf][2], sacc[nf][3]));
        }
        mx0 = fmaxf(mx0, __shfl_xor_sync(0xffffffffu, mx0, 1));
        mx0 = fmaxf(mx0, __shfl_xor_sync(0xffffffffu, mx0, 2));
        mx1 = fmaxf(mx1, __shfl_xor_sync(0xffffffffu, mx1, 1));
        mx1 = fmaxf(mx1, __shfl_xor_sync(0xffffffffu, mx1, 2));
        float mn0 = fmaxf(m0, mx0), mn1 = fmaxf(m1, mx1);
        float al0 = __expf(m0 - mn0), al1 = __expf(m1 - mn1);
        m0 = mn0; m1 = mn1;
        float s0 = 0.f, s1 = 0.f;
        #pragma unroll
        for (int nf = 0; nf < 16; nf++) {
            sacc[nf][0] = __expf(sacc[nf][0] - mn0); s0 += sacc[nf][0];
            sacc[nf][1] = __expf(sacc[nf][1] - mn0); s0 += sacc[nf][1];
            sacc[nf][2] = __expf(sacc[nf][2] - mn1); s1 += sacc[nf][2];
            sacc[nf][3] = __expf(sacc[nf][3] - mn1); s1 += sacc[nf][3];
        }
        s0 += __shfl_xor_sync(0xffffffffu, s0, 1);
        s0 += __shfl_xor_sync(0xffffffffu, s0, 2);
        s1 += __shfl_xor_sync(0xffffffffu, s1, 1);
        s1 += __shfl_xor_sync(0xffffffffu, s1, 2);
        l0 = l0 * al0 + s0;
        l1 = l1 * al1 + s1;
        #pragma unroll
        for (int nf = 0; nf < 16; nf++) {
            oacc[nf][0] *= al0; oacc[nf][1] *= al0;
            oacc[nf][2] *= al1; oacc[nf][3] *= al1;
        }

        #pragma unroll
        for (int kc = 0; kc < 8; kc++) {
            uint32_t pa[4];
            pa[0] = pack2(sacc[2 * kc][0],     sacc[2 * kc][1]);
            pa[1] = pack2(sacc[2 * kc][2],     sacc[2 * kc][3]);
            pa[2] = pack2(sacc[2 * kc + 1][0], sacc[2 * kc + 1][1]);
            pa[3] = pack2(sacc[2 * kc + 1][2], sacc[2 * kc + 1][3]);
            #pragma unroll
            for (int dg2 = 0; dg2 < 8; dg2++) {
                uint32_t bv[4];
                uint32_t addr = Vt + SWZ(kc * 16 + vb_row, dg2 * 2 + vb_c);
                LDSM4T(bv[0], bv[1], bv[2], bv[3], addr);
                MMAF16(oacc[dg2 * 2],     pa, bv);
                MMAF16(oacc[dg2 * 2 + 1], pa, bv + 2);
            }
        }
        __syncthreads();
    }

    float inv0 = 1.f / l0, inv1 = 1.f / l1;
    int gr = qb * 128 + warp * 16 + row0;
    #pragma unroll
    for (int nf = 0; nf < 16; nf++) {
        int col = h * HD + nf * 8 + (lane & 3) * 2;
        *(__half2*)(ctx + (size_t)(b * SS + gr) * HIDD + col) =
            __floats2half2_rn(oacc[nf][0] * inv0, oacc[nf][1] * inv0);
        *(__half2*)(ctx + (size_t)(b * SS + gr + 8) * HIDD + col) =
            __floats2half2_rn(oacc[nf][2] * inv1, oacc[nf][3] * inv1);
    }
}

// ============================================================
// launch
// ============================================================
extern "C" void kernel_launch(void* const* d_in, const int* in_sizes, int n_in,
                              void* d_out, int out_size)
{
    const float* query = (const float*)d_in[0];
    const float* key   = (const float*)d_in[1];
    const float* value = (const float*)d_in[2];
    const float* fcos  = (const float*)d_in[4];
    const float* fsin  = (const float*)d_in[5];
    const float* Wq = (const float*)d_in[6];
    const float* bq = (const float*)d_in[7];
    const float* Wk = (const float*)d_in[8];
    const float* bk = (const float*)d_in[9];
    const float* Wv = (const float*)d_in[10];
    const float* bv = (const float*)d_in[11];
    const float* Wo = (const float*)d_in[12];
    const float* bo = (const float*)d_in[13];
    float* out = (float*)d_out;

    __half *Af, *Wf, *qh, *kh, *vh, *ctxh;
    cudaGetSymbolAddress((void**)&Af,   g_Af);
    cudaGetSymbolAddress((void**)&Wf,   g_Wf);
    cudaGetSymbolAddress((void**)&qh,   g_qh);
    cudaGetSymbolAddress((void**)&kh,   g_kh);
    cudaGetSymbolAddress((void**)&vh,   g_vh);
    cudaGetSymbolAddress((void**)&ctxh, g_ctxh);

    cudaFuncSetAttribute(gemm_f16<0>,
                         cudaFuncAttributeMaxDynamicSharedMemorySize, GEMM_SMEM);
    cudaFuncSetAttribute(gemm_f16<1>,
                         cudaFuncAttributeMaxDynamicSharedMemorySize, GEMM_SMEM);
    cudaFuncSetAttribute(gemm_f16<2>,
                         cudaFuncAttributeMaxDynamicSharedMemorySize, GEMM_SMEM);
    cudaFuncSetAttribute(attn_f16,
                         cudaFuncAttributeMaxDynamicSharedMemorySize, ATT_SMEM);

    const int ACONV_BLKS = (MR * HIDD) / 1024;   // 8192
    const float QSCALE = 0.08838834764831845f;   // 1/sqrt(128)

    // ---- Q projection (+RoPE, scaled) ----
    aconv<<<ACONV_BLKS, 256>>>(query, Af);
    wconv<<<dim3(HIDD / 32, HIDD / 32), 256>>>(Wq, Wf, HIDD, HIDD);
    gemm_f16<1><<<dim3(HIDD / 128, MR / 128), 256, GEMM_SMEM>>>(
        Af, Wf, bq, qh, fcos, fsin, HIDD, QSCALE);

    // ---- K projection (+RoPE) ----
    aconv<<<ACONV_BLKS, 256>>>(key, Af);
    wconv<<<dim3(KVD / 32, HIDD / 32), 256>>>(Wk, Wf, HIDD, KVD);
    gemm_f16<1><<<dim3(KVD / 128, MR / 128), 256, GEMM_SMEM>>>(
        Af, Wf, bk, kh, fcos, fsin, KVD, 1.0f);

    // ---- V projection (fp16 transpose out) ----
    aconv<<<ACONV_BLKS, 256>>>(value, Af);
    wconv<<<dim3(KVD / 32, HIDD / 32), 256>>>(Wv, Wf, HIDD, KVD);
    gemm_f16<2><<<dim3(KVD / 128, MR / 128), 256, GEMM_SMEM>>>(
        Af, Wf, bv, vh, nullptr, nullptr, KVD, 1.0f);

    // ---- attention ----
    attn_f16<<<dim3(SS / 128, NH, BB), 256, ATT_SMEM>>>(qh, kh, vh, ctxh);

    // ---- O projection (fp32 out) ----
    wconv<<<dim3(HIDD / 32, HIDD / 32), 256>>>(Wo, Wf, HIDD, HIDD);
    gemm_f16<0><<<dim3(HIDD / 128, MR / 128), 256, GEMM_SMEM>>>(
        ctxh, Wf, bo, out, nullptr, nullptr, HIDD, 1.0f);
}

// round 14
// speedup vs baseline: 7.8770x; 1.0144x over previous
#include <cuda_runtime.h>
#include <cuda_bf16.h>
#include <cuda_fp16.h>
#include <math.h>
#include <stdint.h>
#include <string.h>

#define BB   2
#define SS   2048
#define HIDD 2048
#define NH   16
#define HD   128
#define NKV  4
#define MR   (BB*SS)          // 4096
#define KVD  (NKV*HD)         // 512

// -------- scratch (device globals; no allocation allowed) --------
__device__ __half g_Afq[MR * HIDD];         // query input fp16
__device__ __half g_Afk[MR * HIDD];         // key input fp16
__device__ __half g_Afv[MR * HIDD];         // value input fp16
__device__ __half g_Wfq[HIDD * HIDD];       // Wq^T fp16 [N,K]
__device__ __half g_Wfk[KVD * HIDD];        // Wk^T fp16
__device__ __half g_Wfv[KVD * HIDD];        // Wv^T fp16
__device__ __half g_Wfo[HIDD * HIDD];       // Wo^T fp16
__device__ __half g_qh[BB * NH * SS * HD];  // roped Q fp16 (pre-scaled)
__device__ __half g_kh[BB * NKV * SS * HD]; // roped K fp16
__device__ __half g_vh[BB * NKV * SS * HD]; // V fp16 [b,kv,s,d]
__device__ __half g_ctxh[MR * HIDD];        // attention output fp16

// ================= helpers =================
__device__ __forceinline__ uint32_t smem_u32(const void* p) {
    uint32_t a;
    asm("{ .reg .u64 t; cvta.to.shared.u64 t, %1; cvt.u32.u64 %0, t; }"
        : "=r"(a) : "l"(p));
    return a;
}

#define CP_ASYNC16(smem, gptr) \
    asm volatile("cp.async.cg.shared.global [%0], [%1], 16;" \
        :: "r"(smem), "l"(gptr))
#define CP_COMMIT() asm volatile("cp.async.commit_group;" ::: "memory")
#define CP_WAIT(n)  asm volatile("cp.async.wait_group %0;" :: "n"(n) : "memory")

#define LDSM4(r0, r1, r2, r3, addr) \
    asm volatile("ldmatrix.sync.aligned.m8n8.x4.shared.b16 {%0,%1,%2,%3}, [%4];" \
        : "=r"(r0), "=r"(r1), "=r"(r2), "=r"(r3) : "r"(addr))

#define LDSM4T(r0, r1, r2, r3, addr) \
    asm volatile("ldmatrix.sync.aligned.m8n8.x4.trans.shared.b16 {%0,%1,%2,%3}, [%4];" \
        : "=r"(r0), "=r"(r1), "=r"(r2), "=r"(r3) : "r"(addr))

#define MMAF16(c, a, b) \
    asm volatile("mma.sync.aligned.m16n8k16.row.col.f32.f16.f16.f32 " \
        "{%0,%1,%2,%3},{%4,%5,%6,%7},{%8,%9},{%0,%1,%2,%3};" \
        : "+f"((c)[0]), "+f"((c)[1]), "+f"((c)[2]), "+f"((c)[3]) \
        : "r"((a)[0]), "r"((a)[1]), "r"((a)[2]), "r"((a)[3]), \
          "r"((b)[0]), "r"((b)[1]))

__device__ __forceinline__ uint32_t pack2(float x, float y) {
    __half2 h = __floats2half2_rn(x, y);
    uint32_t u;
    memcpy(&u, &h, 4);
    return u;
}

// ============================================================
// merged fp16 conversion: query+key+value in one launch
// ============================================================
#define ACONV_BPT 8192   // blocks per tensor

__global__ __launch_bounds__(256)
void aconv_all(const float* __restrict__ q, const float* __restrict__ k,
               const float* __restrict__ v,
               __half* __restrict__ oq, __half* __restrict__ ok,
               __half* __restrict__ ov)
{
    int bid = blockIdx.x;
    const float* A;
    __half* O;
    if (bid < ACONV_BPT)            { A = q; O = oq; }
    else if (bid < 2 * ACONV_BPT)   { A = k; O = ok; bid -= ACONV_BPT; }
    else                            { A = v; O = ov; bid -= 2 * ACONV_BPT; }
    size_t i = ((size_t)bid * 256 + threadIdx.x) * 4;
    float4 val = *(const float4*)(A + i);
    union { __half2 h[2]; uint2 u; } H;
    H.h[0] = __floats2half2_rn(val.x, val.y);
    H.h[1] = __floats2half2_rn(val.z, val.w);
    *(uint2*)(O + i) = H.u;
}

// ============================================================
// merged W transpose+convert: Wq, Wk, Wv, Wo in one launch
// W [2048, Nd] fp32 -> Wt [Nd, 2048] fp16.  Kd = HIDD always.
// ============================================================
#define WQ_BLKS (64 * 64)   // 4096
#define WK_BLKS (16 * 64)   // 1024

__global__ __launch_bounds__(256)
void wconv_all(const float* __restrict__ Wq, const float* __restrict__ Wk,
               const float* __restrict__ Wv, const float* __restrict__ Wo,
               __half* __restrict__ Oq, __half* __restrict__ Ok,
               __half* __restrict__ Ov, __half* __restrict__ Oo)
{
    int bid = blockIdx.x;
    const float* W;
    __half* O;
    int Nd, nx;
    if (bid < WQ_BLKS) { W = Wq; O = Oq; Nd = HIDD; nx = 64; }
    else if (bid < WQ_BLKS + WK_BLKS) {
        W = Wk; O = Ok; Nd = KVD; nx = 16; bid -= WQ_BLKS;
    } else if (bid < WQ_BLKS + 2 * WK_BLKS) {
        W = Wv; O = Ov; Nd = KVD; nx = 16; bid -= WQ_BLKS + WK_BLKS;
    } else {
        W = Wo; O = Oo; Nd = HIDD; nx = 64; bid -= WQ_BLKS + 2 * WK_BLKS;
    }
    int n0 = (bid % nx) * 32;
    int k0 = (bid / nx) * 32;

    __shared__ float s[32][33];
    int r = threadIdx.x >> 5, c = threadIdx.x & 31;
    #pragma unroll
    for (int j = 0; j < 4; j++)
        s[r + 8 * j][c] = W[(size_t)(k0 + r + 8 * j) * Nd + n0 + c];
    __syncthreads();
    #pragma unroll
    for (int j = 0; j < 4; j++)
        O[(size_t)(n0 + r + 8 * j) * HIDD + k0 + c] = __float2half(s[c][r + 8 * j]);
}

// ============================================================
// shared GEMM body (validated inner loop, runtime epilogue mode)
// mode 0: fp32 out + bias (row-major [M,N])
// mode 1: bias + RoPE + scale -> fp16 out [b, h, s, d]
// mode 2: bias -> fp16 out [b, h, s, d]
// ============================================================
#define GBK      64
#define NCH      (HIDD / GBK)        // 32
#define TILE_B   16384
#define STAGE_B  (2 * TILE_B)
#define NSTAGE   3
#define GEMM_SMEM (NSTAGE * STAGE_B) // 98304

__device__ __forceinline__
void gemm_body(const __half* __restrict__ A, const __half* __restrict__ B,
               const float* __restrict__ bias, void* __restrict__ Cout,
               const float* __restrict__ cs, const float* __restrict__ sn,
               int N, float scale, int mode, int bx, int by)
{
    extern __shared__ char smem[];
    const uint32_t smem_base = smem_u32(smem);

    const int tid  = threadIdx.x;
    const int lane = tid & 31;
    const int warp = tid >> 5;
    const int bm = by * 128;
    const int bn = bx * 128;

    const int m0 = (warp >> 1) * 32;
    const int n0 = (warp & 1) * 64;

    float acc[2][8][4];
    #pragma unroll
    for (int mt = 0; mt < 2; mt++)
        #pragma unroll
        for (int nf = 0; nf < 8; nf++)
            #pragma unroll
            for (int q = 0; q < 4; q++) acc[mt][nf][q] = 0.f;

    const int a_row = m0 + (lane & 15);
    const int a_c8  = (lane >> 4);
    const int b_row = n0 + (lane & 7) + ((lane >> 4) << 3);
    const int b_c8  = (lane >> 3) & 1;

    auto load_stage = [&](int s, int k0) {
        uint32_t sb = smem_base + s * STAGE_B;
        #pragma unroll
        for (int t = 0; t < 4; t++) {
            int cc = tid + 256 * t;
            int r = cc >> 3, c = cc & 7;
            uint32_t off = (uint32_t)(r * 128 + ((c ^ (r & 7)) << 4));
            CP_ASYNC16(sb + off,
                       A + (size_t)(bm + r) * HIDD + k0 + c * 8);
            CP_ASYNC16(sb + TILE_B + off,
                       B + (size_t)(bn + r) * HIDD + k0 + c * 8);
        }
    };

    load_stage(0, 0);
    CP_COMMIT();
    load_stage(1, GBK);
    CP_COMMIT();

    for (int ch = 0; ch < NCH; ch++) {
        if (ch == NCH - 1) { CP_WAIT(0); } else { CP_WAIT(1); }
        __syncthreads();
        if (ch + 2 < NCH) {
            load_stage((ch + 2) % NSTAGE, (ch + 2) * GBK);
            CP_COMMIT();
        }

        const uint32_t sb = smem_base + (ch % NSTAGE) * STAGE_B;
        #pragma unroll
        for (int kk = 0; kk < 4; kk++) {
            uint32_t a[2][4];
            #pragma unroll
            for (int mt = 0; mt < 2; mt++) {
                int row = a_row + mt * 16;
                int ca = kk * 2 + a_c8;
                uint32_t addr = sb + (uint32_t)(row * 128 + ((ca ^ (row & 7)) << 4));
                LDSM4(a[mt][0], a[mt][1], a[mt][2], a[mt][3], addr);
            }
            #pragma unroll
            for (int nf2 = 0; nf2 < 4; nf2++) {
                int row = b_row + nf2 * 16;
                int cb = kk * 2 + b_c8;
                uint32_t addr = sb + TILE_B
                              + (uint32_t)(row * 128 + ((cb ^ (row & 7)) << 4));
                uint32_t b[2][2];
                LDSM4(b[0][0], b[0][1], b[1][0], b[1][1], addr);
                #pragma unroll
                for (int half = 0; half < 2; half++) {
                    const int nf = nf2 * 2 + half;
                    #pragma unroll
                    for (int mt = 0; mt < 2; mt++)
                        MMAF16(acc[mt][nf], a[mt], b[half]);
                }
            }
        }
        __syncthreads();
    }

    // ---- fused epilogue ----
    #pragma unroll
    for (int mt = 0; mt < 2; mt++) {
        int grow0 = bm + m0 + mt * 16 + (lane >> 2);
        #pragma unroll
        for (int nf = 0; nf < 8; nf++) {
            int gcol = bn + n0 + nf * 8 + (lane & 3) * 2;
            float2 bv = *(const float2*)(bias + gcol);
            #pragma unroll
            for (int hf = 0; hf < 2; hf++) {
                int r = grow0 + hf * 8;
                float x0 = acc[mt][nf][hf * 2 + 0] + bv.x;
                float x1 = acc[mt][nf][hf * 2 + 1] + bv.y;
                if (mode == 0) {
                    *(float2*)((float*)Cout + (size_t)r * N + gcol) =
                        make_float2(x0, x1);
                } else {
                    int bb = r / SS, s = r % SS;
                    int hh = gcol / HD, d = gcol % HD;
                    size_t o = ((size_t)(bb * (N / HD) + hh) * SS + s) * HD + d;
                    if (mode == 1) {
                        int p = d >> 1;
                        float c  = cs[s * 64 + p];
                        float si = sn[s * 64 + p];
                        float re = (x0 * c - x1 * si) * scale;
                        float im = (x0 * si + x1 * c) * scale;
                        *(__half2*)((__half*)Cout + o) = __floats2half2_rn(re, im);
                    } else {
                        *(__half2*)((__half*)Cout + o) = __floats2half2_rn(x0, x1);
                    }
                }
            }
        }
    }
}

// ---- merged Q+K+V projection launch: 768 blocks ----
#define QG_BLKS 512   // 16 x 32
#define KG_BLKS 128   // 4 x 32

__global__ __launch_bounds__(256)
void gemm_qkv(const __half* __restrict__ Aq, const __half* __restrict__ Ak,
              const __half* __restrict__ Av,
              const __half* __restrict__ Wq, const __half* __restrict__ Wk,
              const __half* __restrict__ Wv,
              const float* __restrict__ bq, const float* __restrict__ bk,
              const float* __restrict__ bv,
              __half* __restrict__ qh, __half* __restrict__ kh,
              __half* __restrict__ vh,
              const float* __restrict__ cs, const float* __restrict__ sn,
              float qscale)
{
    int bid = blockIdx.x;
    if (bid < QG_BLKS) {
        gemm_body(Aq, Wq, bq, qh, cs, sn, HIDD, qscale, 1,
                  bid & 15, bid >> 4);
    } else if (bid < QG_BLKS + KG_BLKS) {
        bid -= QG_BLKS;
        gemm_body(Ak, Wk, bk, kh, cs, sn, KVD, 1.0f, 1,
                  bid & 3, bid >> 2);
    } else {
        bid -= QG_BLKS + KG_BLKS;
        gemm_body(Av, Wv, bv, vh, nullptr, nullptr, KVD, 1.0f, 2,
                  bid & 3, bid >> 2);
    }
}

// ---- O projection launch ----
__global__ __launch_bounds__(256)
void gemm_out(const __half* __restrict__ A, const __half* __restrict__ B,
              const float* __restrict__ bias, float* __restrict__ C)
{
    gemm_body(A, B, bias, C, nullptr, nullptr, HIDD, 1.0f, 0,
              blockIdx.x, blockIdx.y);
}

// ============================================================
// fp16 mma flash attention (validated) — writes fp16 ctx
// ============================================================
#define ATT_SMEM (5 * 32768)
#define SWZ(r, c) ((uint32_t)((r) * 256 + (((((c) ^ (r)) & 7) | ((c) & 8)) << 4)))

__global__ __launch_bounds__(256, 1)
void attn_f16(const __half* __restrict__ Qg, const __half* __restrict__ Kg,
              const __half* __restrict__ Vg, __half* __restrict__ ctx)
{
    extern __shared__ char smem[];
    const uint32_t sb = smem_u32(smem);
    const uint32_t Qs = sb;

    const int tid  = threadIdx.x;
    const int lane = tid & 31;
    const int warp = tid >> 5;
    const int qb = (int)gridDim.x - 1 - (int)blockIdx.x;
    const int h = blockIdx.y, b = blockIdx.z;
    const int kvh = h >> 2;

    const __half* Qbase = Qg + ((size_t)(b * NH + h) * SS + qb * 128) * HD;
    const __half* Kbase = Kg + ((size_t)(b * NKV + kvh) * SS) * HD;
    const __half* Vbase = Vg + ((size_t)(b * NKV + kvh) * SS) * HD;

    #pragma unroll
    for (int it = 0; it < 8; it++) {
        int lin = tid + 256 * it;
        int r = lin >> 4, c = lin & 15;
        CP_ASYNC16(Qs + SWZ(r, c), Qbase + r * HD + c * 8);
    }
    CP_COMMIT();

    auto load_kv = [&](int s, int k0) {
        uint32_t Kt = sb + 32768 + s * 65536;
        #pragma unroll
        for (int it = 0; it < 8; it++) {
            int lin = tid + 256 * it;
            int r = lin >> 4, c = lin & 15;
            uint32_t off = SWZ(r, c);
            CP_ASYNC16(Kt + off,         Kbase + (size_t)(k0 + r) * HD + c * 8);
            CP_ASYNC16(Kt + 32768 + off, Vbase + (size_t)(k0 + r) * HD + c * 8);
        }
    };
    load_kv(0, 0);
    CP_COMMIT();
    CP_WAIT(0);
    __syncthreads();

    uint32_t qa[8][4];
    {
        int ar = warp * 16 + (lane & 15);
        int ahi = lane >> 4;
        #pragma unroll
        for (int kk = 0; kk < 8; kk++) {
            uint32_t addr = Qs + SWZ(ar, kk * 2 + ahi);
            LDSM4(qa[kk][0], qa[kk][1], qa[kk][2], qa[kk][3], addr);
        }
    }

    float oacc[16][4];
    #pragma unroll
    for (int nf = 0; nf < 16; nf++)
        #pragma unroll
        for (int q = 0; q < 4; q++) oacc[nf][q] = 0.f;

    float m0 = -1e30f, m1 = -1e30f, l0 = 0.f, l1 = 0.f;
    const int row0 = lane >> 2;

    const int kb_row = (lane & 7) + ((lane >> 4) << 3);
    const int kb_c   = (lane >> 3) & 1;
    const int vb_row = (lane & 7) + (((lane >> 3) & 1) << 3);
    const int vb_c   = lane >> 4;

    const int ntiles = qb + 1;
    for (int t = 0; t < ntiles; t++) {
        if (t + 1 < ntiles) {
            load_kv((t + 1) & 1, (t + 1) * 128);
            CP_COMMIT();
            CP_WAIT(1);
        } else {
            CP_WAIT(0);
        }
        __syncthreads();
        const uint32_t Kt = sb + 32768 + (t & 1) * 65536;
        const uint32_t Vt = Kt + 32768;

        float sacc[16][4];
        #pragma unroll
        for (int nf = 0; nf < 16; nf++)
            #pragma unroll
            for (int q = 0; q < 4; q++) sacc[nf][q] = 0.f;

        #pragma unroll
        for (int kk = 0; kk < 8; kk++) {
            #pragma unroll
            for (int nf2 = 0; nf2 < 8; nf2++) {
                uint32_t bk[4];
                uint32_t addr = Kt + SWZ(nf2 * 16 + kb_row, kk * 2 + kb_c);
                LDSM4(bk[0], bk[1], bk[2], bk[3], addr);
                MMAF16(sacc[nf2 * 2],     qa[kk], bk);
                MMAF16(sacc[nf2 * 2 + 1], qa[kk], bk + 2);
            }
        }

        if (t == qb) {
            int qg = warp * 16 + row0;
            #pragma unroll
            for (int nf = 0; nf < 16; nf++) {
                int kg = nf * 8 + (lane & 3) * 2;
                if (kg > qg)         sacc[nf][0] = -1e30f;
                if (kg + 1 > qg)     sacc[nf][1] = -1e30f;
                if (kg > qg + 8)     sacc[nf][2] = -1e30f;
                if (kg + 1 > qg + 8) sacc[nf][3] = -1e30f;
            }
        }

        float mx0 = -1e30f, mx1 = -1e30f;
        #pragma unroll
        for (int nf = 0; nf < 16; nf++) {
            mx0 = fmaxf(mx0, fmaxf(sacc[nf][0], sacc[nf][1]));
            mx1 = fmaxf(mx1, fmaxf(sacc[nf][2], sacc[nf][3]));
        }
        mx0 = fmaxf(mx0, __shfl_xor_sync(0xffffffffu, mx0, 1));
        mx0 = fmaxf(mx0, __shfl_xor_sync(0xffffffffu, mx0, 2));
        mx1 = fmaxf(mx1, __shfl_xor_sync(0xffffffffu, mx1, 1));
        mx1 = fmaxf(mx1, __shfl_xor_sync(0xffffffffu, mx1, 2));
        float mn0 = fmaxf(m0, mx0), mn1 = fmaxf(m1, mx1);
        float al0 = __expf(m0 - mn0), al1 = __expf(m1 - mn1);
        m0 = mn0; m1 = mn1;
        float s0 = 0.f, s1 = 0.f;
        #pragma unroll
        for (int nf = 0; nf < 16; nf++) {
            sacc[nf][0] = __expf(sacc[nf][0] - mn0); s0 += sacc[nf][0];
            sacc[nf][1] = __expf(sacc[nf][1] - mn0); s0 += sacc[nf][1];
            sacc[nf][2] = __expf(sacc[nf][2] - mn1); s1 += sacc[nf][2];
            sacc[nf][3] = __expf(sacc[nf][3] - mn1); s1 += sacc[nf][3];
        }
        s0 += __shfl_xor_sync(0xffffffffu, s0, 1);
        s0 += __shfl_xor_sync(0xffffffffu, s0, 2);
        s1 += __shfl_xor_sync(0xffffffffu, s1, 1);
        s1 += __shfl_xor_sync(0xffffffffu, s1, 2);
        l0 = l0 * al0 + s0;
        l1 = l1 * al1 + s1;
        #pragma unroll
        for (int nf = 0; nf < 16; nf++) {
            oacc[nf][0] *= al0; oacc[nf][1] *= al0;
            oacc[nf][2] *= al1; oacc[nf][3] *= al1;
        }

        #pragma unroll
        for (int kc = 0; kc < 8; kc++) {
            uint32_t pa[4];
            pa[0] = pack2(sacc[2 * kc][0],     sacc[2 * kc][1]);
            pa[1] = pack2(sacc[2 * kc][2],     sacc[2 * kc][3]);
            pa[2] = pack2(sacc[2 * kc + 1][0], sacc[2 * kc + 1][1]);
            pa[3] = pack2(sacc[2 * kc + 1][2], sacc[2 * kc + 1][3]);
            #pragma unroll
            for (int dg2 = 0; dg2 < 8; dg2++) {
                uint32_t bv[4];
                uint32_t addr = Vt + SWZ(kc * 16 + vb_row, dg2 * 2 + vb_c);
                LDSM4T(bv[0], bv[1], bv[2], bv[3], addr);
                MMAF16(oacc[dg2 * 2],     pa, bv);
                MMAF16(oacc[dg2 * 2 + 1], pa, bv + 2);
            }
        }
        __syncthreads();
    }

    float inv0 = 1.f / l0, inv1 = 1.f / l1;
    int gr = qb * 128 + warp * 16 + row0;
    #pragma unroll
    for (int nf = 0; nf < 16; nf++) {
        int col = h * HD + nf * 8 + (lane & 3) * 2;
        *(__half2*)(ctx + (size_t)(b * SS + gr) * HIDD + col) =
            __floats2half2_rn(oacc[nf][0] * inv0, oacc[nf][1] * inv0);
        *(__half2*)(ctx + (size_t)(b * SS + gr + 8) * HIDD + col) =
            __floats2half2_rn(oacc[nf][2] * inv1, oacc[nf][3] * inv1);
    }
}

// ============================================================
// launch
// ============================================================
extern "C" void kernel_launch(void* const* d_in, const int* in_sizes, int n_in,
                              void* d_out, int out_size)
{
    const float* query = (const float*)d_in[0];
    const float* key   = (const float*)d_in[1];
    const float* value = (const float*)d_in[2];
    const float* fcos  = (const float*)d_in[4];
    const float* fsin  = (const float*)d_in[5];
    const float* Wq = (const float*)d_in[6];
    const float* bq = (const float*)d_in[7];
    const float* Wk = (const float*)d_in[8];
    const float* bk = (const float*)d_in[9];
    const float* Wv = (const float*)d_in[10];
    const float* bv = (const float*)d_in[11];
    const float* Wo = (const float*)d_in[12];
    const float* bo = (const float*)d_in[13];
    float* out = (float*)d_out;

    __half *Afq, *Afk, *Afv, *Wfq, *Wfk, *Wfv, *Wfo, *qh, *kh, *vh, *ctxh;
    cudaGetSymbolAddress((void**)&Afq,  g_Afq);
    cudaGetSymbolAddress((void**)&Afk,  g_Afk);
    cudaGetSymbolAddress((void**)&Afv,  g_Afv);
    cudaGetSymbolAddress((void**)&Wfq,  g_Wfq);
    cudaGetSymbolAddress((void**)&Wfk,  g_Wfk);
    cudaGetSymbolAddress((void**)&Wfv,  g_Wfv);
    cudaGetSymbolAddress((void**)&Wfo,  g_Wfo);
    cudaGetSymbolAddress((void**)&qh,   g_qh);
    cudaGetSymbolAddress((void**)&kh,   g_kh);
    cudaGetSymbolAddress((void**)&vh,   g_vh);
    cudaGetSymbolAddress((void**)&ctxh, g_ctxh);

    cudaFuncSetAttribute(gemm_qkv,
                         cudaFuncAttributeMaxDynamicSharedMemorySize, GEMM_SMEM);
    cudaFuncSetAttribute(gemm_out,
                         cudaFuncAttributeMaxDynamicSharedMemorySize, GEMM_SMEM);
    cudaFuncSetAttribute(attn_f16,
                         cudaFuncAttributeMaxDynamicSharedMemorySize, ATT_SMEM);

    const float QSCALE = 0.08838834764831845f;   // 1/sqrt(128)

    // 1) convert Q/K/V inputs to fp16
    aconv_all<<<3 * ACONV_BPT, 256>>>(query, key, value, Afq, Afk, Afv);

    // 2) transpose+convert all four weight matrices
    wconv_all<<<2 * WQ_BLKS + 2 * WK_BLKS, 256>>>(Wq, Wk, Wv, Wo,
                                                  Wfq, Wfk, Wfv, Wfo);

    // 3) merged Q/K/V projections (+RoPE / layout epilogues)
    gemm_qkv<<<QG_BLKS + 2 * KG_BLKS, 256, GEMM_SMEM>>>(
        Afq, Afk, Afv, Wfq, Wfk, Wfv, bq, bk, bv,
        qh, kh, vh, fcos, fsin, QSCALE);

    // 4) attention
    attn_f16<<<dim3(SS / 128, NH, BB), 256, ATT_SMEM>>>(qh, kh, vh, ctxh);

    // 5) O projection (fp32 out)
    gemm_out<<<dim3(HIDD / 128, MR / 128), 256, GEMM_SMEM>>>(ctxh, Wfo, bo, out);
}

// round 16
// speedup vs baseline: 8.0055x; 1.0163x over previous
#include <cuda_runtime.h>
#include <cuda_bf16.h>
#include <cuda_fp16.h>
#include <math.h>
#include <stdint.h>
#include <string.h>

#define BB   2
#define SS   2048
#define HIDD 2048
#define NH   16
#define HD   128
#define NKV  4
#define MR   (BB*SS)          // 4096
#define KVD  (NKV*HD)         // 512

// -------- scratch (device globals; no allocation allowed) --------
__device__ __half g_Afq[MR * HIDD];         // query input fp16
__device__ __half g_Afk[MR * HIDD];         // key input fp16
__device__ __half g_Afv[MR * HIDD];         // value input fp16
__device__ __half g_Wfq[HIDD * HIDD];       // Wq^T fp16 [N,K]
__device__ __half g_Wfk[KVD * HIDD];        // Wk^T fp16
__device__ __half g_Wfv[KVD * HIDD];        // Wv^T fp16
__device__ __half g_Wfo[HIDD * HIDD];       // Wo^T fp16
__device__ __half g_qh[BB * NH * SS * HD];  // roped Q fp16 (pre-scaled)
__device__ __half g_kh[BB * NKV * SS * HD]; // roped K fp16
__device__ __half g_vh[BB * NKV * SS * HD]; // V fp16 [b,kv,s,d]
__device__ __half g_ctxh[MR * HIDD];        // attention output fp16

// ================= helpers =================
__device__ __forceinline__ uint32_t smem_u32(const void* p) {
    uint32_t a;
    asm("{ .reg .u64 t; cvta.to.shared.u64 t, %1; cvt.u32.u64 %0, t; }"
        : "=r"(a) : "l"(p));
    return a;
}

#define CP_ASYNC16(smem, gptr) \
    asm volatile("cp.async.cg.shared.global [%0], [%1], 16;" \
        :: "r"(smem), "l"(gptr))
#define CP_COMMIT() asm volatile("cp.async.commit_group;" ::: "memory")
#define CP_WAIT(n)  asm volatile("cp.async.wait_group %0;" :: "n"(n) : "memory")

#define LDSM4(r0, r1, r2, r3, addr) \
    asm volatile("ldmatrix.sync.aligned.m8n8.x4.shared.b16 {%0,%1,%2,%3}, [%4];" \
        : "=r"(r0), "=r"(r1), "=r"(r2), "=r"(r3) : "r"(addr))

#define LDSM4T(r0, r1, r2, r3, addr) \
    asm volatile("ldmatrix.sync.aligned.m8n8.x4.trans.shared.b16 {%0,%1,%2,%3}, [%4];" \
        : "=r"(r0), "=r"(r1), "=r"(r2), "=r"(r3) : "r"(addr))

#define MMAF16(c, a, b) \
    asm volatile("mma.sync.aligned.m16n8k16.row.col.f32.f16.f16.f32 " \
        "{%0,%1,%2,%3},{%4,%5,%6,%7},{%8,%9},{%0,%1,%2,%3};" \
        : "+f"((c)[0]), "+f"((c)[1]), "+f"((c)[2]), "+f"((c)[3]) \
        : "r"((a)[0]), "r"((a)[1]), "r"((a)[2]), "r"((a)[3]), \
          "r"((b)[0]), "r"((b)[1]))

__device__ __forceinline__ uint32_t pack2(float x, float y) {
    __half2 h = __floats2half2_rn(x, y);
    uint32_t u;
    memcpy(&u, &h, 4);
    return u;
}

// ============================================================
// merged fp16 conversion: query+key+value in one launch
// ============================================================
#define ACONV_BPT 8192   // blocks per tensor

__global__ __launch_bounds__(256)
void aconv_all(const float* __restrict__ q, const float* __restrict__ k,
               const float* __restrict__ v,
               __half* __restrict__ oq, __half* __restrict__ ok,
               __half* __restrict__ ov)
{
    int bid = blockIdx.x;
    const float* A;
    __half* O;
    if (bid < ACONV_BPT)            { A = q; O = oq; }
    else if (bid < 2 * ACONV_BPT)   { A = k; O = ok; bid -= ACONV_BPT; }
    else                            { A = v; O = ov; bid -= 2 * ACONV_BPT; }
    size_t i = ((size_t)bid * 256 + threadIdx.x) * 4;
    float4 val = *(const float4*)(A + i);
    union { __half2 h[2]; uint2 u; } H;
    H.h[0] = __floats2half2_rn(val.x, val.y);
    H.h[1] = __floats2half2_rn(val.z, val.w);
    *(uint2*)(O + i) = H.u;
}

// ============================================================
// merged W transpose+convert: Wq, Wk, Wv, Wo in one launch
// ============================================================
#define WQ_BLKS (64 * 64)   // 4096
#define WK_BLKS (16 * 64)   // 1024

__global__ __launch_bounds__(256)
void wconv_all(const float* __restrict__ Wq, const float* __restrict__ Wk,
               const float* __restrict__ Wv, const float* __restrict__ Wo,
               __half* __restrict__ Oq, __half* __restrict__ Ok,
               __half* __restrict__ Ov, __half* __restrict__ Oo)
{
    int bid = blockIdx.x;
    const float* W;
    __half* O;
    int Nd, nx;
    if (bid < WQ_BLKS) { W = Wq; O = Oq; Nd = HIDD; nx = 64; }
    else if (bid < WQ_BLKS + WK_BLKS) {
        W = Wk; O = Ok; Nd = KVD; nx = 16; bid -= WQ_BLKS;
    } else if (bid < WQ_BLKS + 2 * WK_BLKS) {
        W = Wv; O = Ov; Nd = KVD; nx = 16; bid -= WQ_BLKS + WK_BLKS;
    } else {
        W = Wo; O = Oo; Nd = HIDD; nx = 64; bid -= WQ_BLKS + 2 * WK_BLKS;
    }
    int n0 = (bid % nx) * 32;
    int k0 = (bid / nx) * 32;

    __shared__ float s[32][33];
    int r = threadIdx.x >> 5, c = threadIdx.x & 31;
    #pragma unroll
    for (int j = 0; j < 4; j++)
        s[r + 8 * j][c] = W[(size_t)(k0 + r + 8 * j) * Nd + n0 + c];
    __syncthreads();
    #pragma unroll
    for (int j = 0; j < 4; j++)
        O[(size_t)(n0 + r + 8 * j) * HIDD + k0 + c] = __float2half(s[c][r + 8 * j]);
}

// ============================================================
// shared GEMM body — block tile 256x128, warp tile 64x64.
// mode 0: fp32 out + bias (row-major [M,N])
// mode 1: bias + RoPE + scale -> fp16 out [b, h, s, d]
// mode 2: bias -> fp16 out [b, h, s, d]
// ============================================================
#define GBK      64
#define NCH      (HIDD / GBK)        // 32
#define TILE_A   32768               // 256 rows x 128 bytes
#define TILE_BB  16384               // 128 rows x 128 bytes
#define STAGE_B  (TILE_A + TILE_BB)  // 49152
#define NSTAGE   3
#define GEMM_SMEM (NSTAGE * STAGE_B) // 147456

__device__ __forceinline__
void gemm_body(const __half* __restrict__ A, const __half* __restrict__ B,
               const float* __restrict__ bias, void* __restrict__ Cout,
               const float* __restrict__ cs, const float* __restrict__ sn,
               int N, float scale, int mode, int bx, int by)
{
    extern __shared__ char smem[];
    const uint32_t smem_base = smem_u32(smem);

    const int tid  = threadIdx.x;
    const int lane = tid & 31;
    const int warp = tid >> 5;
    const int bm = by * 256;
    const int bn = bx * 128;

    const int m0 = (warp >> 1) * 64;
    const int n0 = (warp & 1) * 64;

    float acc[4][8][4];
    #pragma unroll
    for (int mt = 0; mt < 4; mt++)
        #pragma unroll
        for (int nf = 0; nf < 8; nf++)
            #pragma unroll
            for (int q = 0; q < 4; q++) acc[mt][nf][q] = 0.f;

    const int a_row = m0 + (lane & 15);
    const int a_c8  = (lane >> 4);
    const int b_row = n0 + (lane & 7) + ((lane >> 4) << 3);
    const int b_c8  = (lane >> 3) & 1;

    auto load_stage = [&](int s, int k0) {
        uint32_t sb = smem_base + s * STAGE_B;
        // A: 256 rows x 8 chunks = 2048 cp.async (8/thread)
        #pragma unroll
        for (int t = 0; t < 8; t++) {
            int cc = tid + 256 * t;
            int r = cc >> 3, c = cc & 7;
            uint32_t off = (uint32_t)(r * 128 + ((c ^ (r & 7)) << 4));
            CP_ASYNC16(sb + off, A + (size_t)(bm + r) * HIDD + k0 + c * 8);
        }
        // B: 128 rows x 8 chunks = 1024 cp.async (4/thread)
        #pragma unroll
        for (int t = 0; t < 4; t++) {
            int cc = tid + 256 * t;
            int r = cc >> 3, c = cc & 7;
            uint32_t off = (uint32_t)(r * 128 + ((c ^ (r & 7)) << 4));
            CP_ASYNC16(sb + TILE_A + off, B + (size_t)(bn + r) * HIDD + k0 + c * 8);
        }
    };

    load_stage(0, 0);
    CP_COMMIT();
    load_stage(1, GBK);
    CP_COMMIT();

    for (int ch = 0; ch < NCH; ch++) {
        if (ch == NCH - 1) { CP_WAIT(0); } else { CP_WAIT(1); }
        __syncthreads();
        if (ch + 2 < NCH) {
            load_stage((ch + 2) % NSTAGE, (ch + 2) * GBK);
            CP_COMMIT();
        }

        const uint32_t sb = smem_base + (ch % NSTAGE) * STAGE_B;
        #pragma unroll
        for (int kk = 0; kk < 4; kk++) {
            uint32_t a[4][4];
            #pragma unroll
            for (int mt = 0; mt < 4; mt++) {
                int row = a_row + mt * 16;
                int ca = kk * 2 + a_c8;
                uint32_t addr = sb + (uint32_t)(row * 128 + ((ca ^ (row & 7)) << 4));
                LDSM4(a[mt][0], a[mt][1], a[mt][2], a[mt][3], addr);
            }
            #pragma unroll
            for (int nf2 = 0; nf2 < 4; nf2++) {
                int row = b_row + nf2 * 16;
                int cb = kk * 2 + b_c8;
                uint32_t addr = sb + TILE_A
                              + (uint32_t)(row * 128 + ((cb ^ (row & 7)) << 4));
                uint32_t b[2][2];
                LDSM4(b[0][0], b[0][1], b[1][0], b[1][1], addr);
                #pragma unroll
                for (int half = 0; half < 2; half++) {
                    const int nf = nf2 * 2 + half;
                    #pragma unroll
                    for (int mt = 0; mt < 4; mt++)
                        MMAF16(acc[mt][nf], a[mt], b[half]);
                }
            }
        }
        __syncthreads();
    }

    // ---- fused epilogue ----
    #pragma unroll
    for (int mt = 0; mt < 4; mt++) {
        int grow0 = bm + m0 + mt * 16 + (lane >> 2);
        #pragma unroll
        for (int nf = 0; nf < 8; nf++) {
            int gcol = bn + n0 + nf * 8 + (lane & 3) * 2;
            float2 bv = *(const float2*)(bias + gcol);
            #pragma unroll
            for (int hf = 0; hf < 2; hf++) {
                int r = grow0 + hf * 8;
                float x0 = acc[mt][nf][hf * 2 + 0] + bv.x;
                float x1 = acc[mt][nf][hf * 2 + 1] + bv.y;
                if (mode == 0) {
                    *(float2*)((float*)Cout + (size_t)r * N + gcol) =
                        make_float2(x0, x1);
                } else {
                    int bb = r / SS, s = r % SS;
                    int hh = gcol / HD, d = gcol % HD;
                    size_t o = ((size_t)(bb * (N / HD) + hh) * SS + s) * HD + d;
                    if (mode == 1) {
                        int p = d >> 1;
                        float c  = cs[s * 64 + p];
                        float si = sn[s * 64 + p];
                        float re = (x0 * c - x1 * si) * scale;
                        float im = (x0 * si + x1 * c) * scale;
                        *(__half2*)((__half*)Cout + o) = __floats2half2_rn(re, im);
                    } else {
                        *(__half2*)((__half*)Cout + o) = __floats2half2_rn(x0, x1);
                    }
                }
            }
        }
    }
}

// ---- merged Q+K+V projection launch ----
#define QG_BLKS 256   // (4096/256) x (2048/128) = 16 x 16
#define KG_BLKS 64    // 16 x 4

__global__ __launch_bounds__(256)
void gemm_qkv(const __half* __restrict__ Aq, const __half* __restrict__ Ak,
              const __half* __restrict__ Av,
              const __half* __restrict__ Wq, const __half* __restrict__ Wk,
              const __half* __restrict__ Wv,
              const float* __restrict__ bq, const float* __restrict__ bk,
              const float* __restrict__ bv,
              __half* __restrict__ qh, __half* __restrict__ kh,
              __half* __restrict__ vh,
              const float* __restrict__ cs, const float* __restrict__ sn,
              float qscale)
{
    int bid = blockIdx.x;
    if (bid < QG_BLKS) {
        gemm_body(Aq, Wq, bq, qh, cs, sn, HIDD, qscale, 1,
                  bid & 15, bid >> 4);
    } else if (bid < QG_BLKS + KG_BLKS) {
        bid -= QG_BLKS;
        gemm_body(Ak, Wk, bk, kh, cs, sn, KVD, 1.0f, 1,
                  bid & 3, bid >> 2);
    } else {
        bid -= QG_BLKS + KG_BLKS;
        gemm_body(Av, Wv, bv, vh, nullptr, nullptr, KVD, 1.0f, 2,
                  bid & 3, bid >> 2);
    }
}

// ---- O projection launch ----
__global__ __launch_bounds__(256)
void gemm_out(const __half* __restrict__ A, const __half* __restrict__ B,
              const float* __restrict__ bias, float* __restrict__ C)
{
    gemm_body(A, B, bias, C, nullptr, nullptr, HIDD, 1.0f, 0,
              blockIdx.x, blockIdx.y);
}

// ============================================================
// fp16 mma flash attention (validated, unchanged)
// ============================================================
#define ATT_SMEM (5 * 32768)
#define SWZ(r, c) ((uint32_t)((r) * 256 + (((((c) ^ (r)) & 7) | ((c) & 8)) << 4)))

__global__ __launch_bounds__(256, 1)
void attn_f16(const __half* __restrict__ Qg, const __half* __restrict__ Kg,
              const __half* __restrict__ Vg, __half* __restrict__ ctx)
{
    extern __shared__ char smem[];
    const uint32_t sb = smem_u32(smem);
    const uint32_t Qs = sb;

    const int tid  = threadIdx.x;
    const int lane = tid & 31;
    const int warp = tid >> 5;
    const int qb = (int)gridDim.x - 1 - (int)blockIdx.x;
    const int h = blockIdx.y, b = blockIdx.z;
    const int kvh = h >> 2;

    const __half* Qbase = Qg + ((size_t)(b * NH + h) * SS + qb * 128) * HD;
    const __half* Kbase = Kg + ((size_t)(b * NKV + kvh) * SS) * HD;
    const __half* Vbase = Vg + ((size_t)(b * NKV + kvh) * SS) * HD;

    #pragma unroll
    for (int it = 0; it < 8; it++) {
        int lin = tid + 256 * it;
        int r = lin >> 4, c = lin & 15;
        CP_ASYNC16(Qs + SWZ(r, c), Qbase + r * HD + c * 8);
    }
    CP_COMMIT();

    auto load_kv = [&](int s, int k0) {
        uint32_t Kt = sb + 32768 + s * 65536;
        #pragma unroll
        for (int it = 0; it < 8; it++) {
            int lin = tid + 256 * it;
            int r = lin >> 4, c = lin & 15;
            uint32_t off = SWZ(r, c);
            CP_ASYNC16(Kt + off,         Kbase + (size_t)(k0 + r) * HD + c * 8);
            CP_ASYNC16(Kt + 32768 + off, Vbase + (size_t)(k0 + r) * HD + c * 8);
        }
    };
    load_kv(0, 0);
    CP_COMMIT();
    CP_WAIT(0);
    __syncthreads();

    uint32_t qa[8][4];
    {
        int ar = warp * 16 + (lane & 15);
        int ahi = lane >> 4;
        #pragma unroll
        for (int kk = 0; kk < 8; kk++) {
            uint32_t addr = Qs + SWZ(ar, kk * 2 + ahi);
            LDSM4(qa[kk][0], qa[kk][1], qa[kk][2], qa[kk][3], addr);
        }
    }

    float oacc[16][4];
    #pragma unroll
    for (int nf = 0; nf < 16; nf++)
        #pragma unroll
        for (int q = 0; q < 4; q++) oacc[nf][q] = 0.f;

    float m0 = -1e30f, m1 = -1e30f, l0 = 0.f, l1 = 0.f;
    const int row0 = lane >> 2;

    const int kb_row = (lane & 7) + ((lane >> 4) << 3);
    const int kb_c   = (lane >> 3) & 1;
    const int vb_row = (lane & 7) + (((lane >> 3) & 1) << 3);
    const int vb_c   = lane >> 4;

    const int ntiles = qb + 1;
    for (int t = 0; t < ntiles; t++) {
        if (t + 1 < ntiles) {
            load_kv((t + 1) & 1, (t + 1) * 128);
            CP_COMMIT();
            CP_WAIT(1);
        } else {
            CP_WAIT(0);
        }
        __syncthreads();
        const uint32_t Kt = sb + 32768 + (t & 1) * 65536;
        const uint32_t Vt = Kt + 32768;

        float sacc[16][4];
        #pragma unroll
        for (int nf = 0; nf < 16; nf++)
            #pragma unroll
            for (int q = 0; q < 4; q++) sacc[nf][q] = 0.f;

        #pragma unroll
        for (int kk = 0; kk < 8; kk++) {
            #pragma unroll
            for (int nf2 = 0; nf2 < 8; nf2++) {
                uint32_t bk[4];
                uint32_t addr = Kt + SWZ(nf2 * 16 + kb_row, kk * 2 + kb_c);
                LDSM4(bk[0], bk[1], bk[2], bk[3], addr);
                MMAF16(sacc[nf2 * 2],     qa[kk], bk);
                MMAF16(sacc[nf2 * 2 + 1], qa[kk], bk + 2);
            }
        }

        if (t == qb) {
            int qg = warp * 16 + row0;
            #pragma unroll
            for (int nf = 0; nf < 16; nf++) {
                int kg = nf * 8 + (lane & 3) * 2;
                if (kg > qg)         sacc[nf][0] = -1e30f;
                if (kg + 1 > qg)     sacc[nf][1] = -1e30f;
                if (kg > qg + 8)     sacc[nf][2] = -1e30f;
                if (kg + 1 > qg + 8) sacc[nf][3] = -1e30f;
            }
        }

        float mx0 = -1e30f, mx1 = -1e30f;
        #pragma unroll
        for (int nf = 0; nf < 16; nf++) {
            mx0 = fmaxf(mx0, fmaxf(sacc[nf][0], sacc[nf][1]));
            mx1 = fmaxf(mx1, fmaxf(sacc[nf][2], sacc[nf][3]));
        }
        mx0 = fmaxf(mx0, __shfl_xor_sync(0xffffffffu, mx0, 1));
        mx0 = fmaxf(mx0, __shfl_xor_sync(0xffffffffu, mx0, 2));
        mx1 = fmaxf(mx1, __shfl_xor_sync(0xffffffffu, mx1, 1));
        mx1 = fmaxf(mx1, __shfl_xor_sync(0xffffffffu, mx1, 2));
        float mn0 = fmaxf(m0, mx0), mn1 = fmaxf(m1, mx1);
        float al0 = __expf(m0 - mn0), al1 = __expf(m1 - mn1);
        m0 = mn0; m1 = mn1;
        float s0 = 0.f, s1 = 0.f;
        #pragma unroll
        for (int nf = 0; nf < 16; nf++) {
            sacc[nf][0] = __expf(sacc[nf][0] - mn0); s0 += sacc[nf][0];
            sacc[nf][1] = __expf(sacc[nf][1] - mn0); s0 += sacc[nf][1];
            sacc[nf][2] = __expf(sacc[nf][2] - mn1); s1 += sacc[nf][2];
            sacc[nf][3] = __expf(sacc[nf][3] - mn1); s1 += sacc[nf][3];
        }
        s0 += __shfl_xor_sync(0xffffffffu, s0, 1);
        s0 += __shfl_xor_sync(0xffffffffu, s0, 2);
        s1 += __shfl_xor_sync(0xffffffffu, s1, 1);
        s1 += __shfl_xor_sync(0xffffffffu, s1, 2);
        l0 = l0 * al0 + s0;
        l1 = l1 * al1 + s1;
        #pragma unroll
        for (int nf = 0; nf < 16; nf++) {
            oacc[nf][0] *= al0; oacc[nf][1] *= al0;
            oacc[nf][2] *= al1; oacc[nf][3] *= al1;
        }

        #pragma unroll
        for (int kc = 0; kc < 8; kc++) {
            uint32_t pa[4];
            pa[0] = pack2(sacc[2 * kc][0],     sacc[2 * kc][1]);
            pa[1] = pack2(sacc[2 * kc][2],     sacc[2 * kc][3]);
            pa[2] = pack2(sacc[2 * kc + 1][0], sacc[2 * kc + 1][1]);
            pa[3] = pack2(sacc[2 * kc + 1][2], sacc[2 * kc + 1][3]);
            #pragma unroll
            for (int dg2 = 0; dg2 < 8; dg2++) {
                uint32_t bv[4];
                uint32_t addr = Vt + SWZ(kc * 16 + vb_row, dg2 * 2 + vb_c);
                LDSM4T(bv[0], bv[1], bv[2], bv[3], addr);
                MMAF16(oacc[dg2 * 2],     pa, bv);
                MMAF16(oacc[dg2 * 2 + 1], pa, bv + 2);
            }
        }
        __syncthreads();
    }

    float inv0 = 1.f / l0, inv1 = 1.f / l1;
    int gr = qb * 128 + warp * 16 + row0;
    #pragma unroll
    for (int nf = 0; nf < 16; nf++) {
        int col = h * HD + nf * 8 + (lane & 3) * 2;
        *(__half2*)(ctx + (size_t)(b * SS + gr) * HIDD + col) =
            __floats2half2_rn(oacc[nf][0] * inv0, oacc[nf][1] * inv0);
        *(__half2*)(ctx + (size_t)(b * SS + gr + 8) * HIDD + col) =
            __floats2half2_rn(oacc[nf][2] * inv1, oacc[nf][3] * inv1);
    }
}

// ============================================================
// launch
// ============================================================
extern "C" void kernel_launch(void* const* d_in, const int* in_sizes, int n_in,
                              void* d_out, int out_size)
{
    const float* query = (const float*)d_in[0];
    const float* key   = (const float*)d_in[1];
    const float* value = (const float*)d_in[2];
    const float* fcos  = (const float*)d_in[4];
    const float* fsin  = (const float*)d_in[5];
    const float* Wq = (const float*)d_in[6];
    const float* bq = (const float*)d_in[7];
    const float* Wk = (const float*)d_in[8];
    const float* bk = (const float*)d_in[9];
    const float* Wv = (const float*)d_in[10];
    const float* bv = (const float*)d_in[11];
    const float* Wo = (const float*)d_in[12];
    const float* bo = (const float*)d_in[13];
    float* out = (float*)d_out;

    __half *Afq, *Afk, *Afv, *Wfq, *Wfk, *Wfv, *Wfo, *qh, *kh, *vh, *ctxh;
    cudaGetSymbolAddress((void**)&Afq,  g_Afq);
    cudaGetSymbolAddress((void**)&Afk,  g_Afk);
    cudaGetSymbolAddress((void**)&Afv,  g_Afv);
    cudaGetSymbolAddress((void**)&Wfq,  g_Wfq);
    cudaGetSymbolAddress((void**)&Wfk,  g_Wfk);
    cudaGetSymbolAddress((void**)&Wfv,  g_Wfv);
    cudaGetSymbolAddress((void**)&Wfo,  g_Wfo);
    cudaGetSymbolAddress((void**)&qh,   g_qh);
    cudaGetSymbolAddress((void**)&kh,   g_kh);
    cudaGetSymbolAddress((void**)&vh,   g_vh);
    cudaGetSymbolAddress((void**)&ctxh, g_ctxh);

    cudaFuncSetAttribute(gemm_qkv,
                         cudaFuncAttributeMaxDynamicSharedMemorySize, GEMM_SMEM);
    cudaFuncSetAttribute(gemm_out,
                         cudaFuncAttributeMaxDynamicSharedMemorySize, GEMM_SMEM);
    cudaFuncSetAttribute(attn_f16,
                         cudaFuncAttributeMaxDynamicSharedMemorySize, ATT_SMEM);

    const float QSCALE = 0.08838834764831845f;   // 1/sqrt(128)

    // 1) convert Q/K/V inputs to fp16
    aconv_all<<<3 * ACONV_BPT, 256>>>(query, key, value, Afq, Afk, Afv);

    // 2) transpose+convert all four weight matrices
    wconv_all<<<2 * WQ_BLKS + 2 * WK_BLKS, 256>>>(Wq, Wk, Wv, Wo,
                                                  Wfq, Wfk, Wfv, Wfo);

    // 3) merged Q/K/V projections (+RoPE / layout epilogues)
    gemm_qkv<<<QG_BLKS + 2 * KG_BLKS, 256, GEMM_SMEM>>>(
        Afq, Afk, Afv, Wfq, Wfk, Wfv, bq, bk, bv,
        qh, kh, vh, fcos, fsin, QSCALE);

    // 4) attention
    attn_f16<<<dim3(SS / 128, NH, BB), 256, ATT_SMEM>>>(qh, kh, vh, ctxh);

    // 5) O projection (fp32 out)
    gemm_out<<<dim3(HIDD / 128, MR / 256), 256, GEMM_SMEM>>>(ctxh, Wfo, bo, out);
}

// round 17
// speedup vs baseline: 8.1498x; 1.0180x over previous
#include <cuda_runtime.h>
#include <cuda_bf16.h>
#include <cuda_fp16.h>
#include <math.h>
#include <stdint.h>
#include <string.h>

#define BB   2
#define SS   2048
#define HIDD 2048
#define NH   16
#define HD   128
#define NKV  4
#define MR   (BB*SS)          // 4096
#define KVD  (NKV*HD)         // 512

// -------- scratch (device globals; no allocation allowed) --------
__device__ __half g_Afq[MR * HIDD];         // query input fp16
__device__ __half g_Afk[MR * HIDD];         // key input fp16
__device__ __half g_Afv[MR * HIDD];         // value input fp16
__device__ __half g_Wfq[HIDD * HIDD];       // Wq^T fp16 [N,K]
__device__ __half g_Wfk[KVD * HIDD];        // Wk^T fp16
__device__ __half g_Wfv[KVD * HIDD];        // Wv^T fp16
__device__ __half g_Wfo[HIDD * HIDD];       // Wo^T fp16
__device__ __half g_qh[BB * NH * SS * HD];  // roped Q fp16 (scaled by log2e/sqrt(D))
__device__ __half g_kh[BB * NKV * SS * HD]; // roped K fp16
__device__ __half g_vh[BB * NKV * SS * HD]; // V fp16 [b,kv,s,d]
__device__ __half g_ctxh[MR * HIDD];        // attention output fp16

// ================= helpers =================
__device__ __forceinline__ uint32_t smem_u32(const void* p) {
    uint32_t a;
    asm("{ .reg .u64 t; cvta.to.shared.u64 t, %1; cvt.u32.u64 %0, t; }"
        : "=r"(a) : "l"(p));
    return a;
}
__device__ __forceinline__ float ex2f(float x) {
    float r;
    asm("ex2.approx.f32 %0, %1;" : "=f"(r) : "f"(x));
    return r;
}

#define CP_ASYNC16(smem, gptr) \
    asm volatile("cp.async.cg.shared.global [%0], [%1], 16;" \
        :: "r"(smem), "l"(gptr))
#define CP_COMMIT() asm volatile("cp.async.commit_group;" ::: "memory")
#define CP_WAIT(n)  asm volatile("cp.async.wait_group %0;" :: "n"(n) : "memory")

#define LDSM4(r0, r1, r2, r3, addr) \
    asm volatile("ldmatrix.sync.aligned.m8n8.x4.shared.b16 {%0,%1,%2,%3}, [%4];" \
        : "=r"(r0), "=r"(r1), "=r"(r2), "=r"(r3) : "r"(addr))

#define LDSM4T(r0, r1, r2, r3, addr) \
    asm volatile("ldmatrix.sync.aligned.m8n8.x4.trans.shared.b16 {%0,%1,%2,%3}, [%4];" \
        : "=r"(r0), "=r"(r1), "=r"(r2), "=r"(r3) : "r"(addr))

#define MMAF16(c, a, b) \
    asm volatile("mma.sync.aligned.m16n8k16.row.col.f32.f16.f16.f32 " \
        "{%0,%1,%2,%3},{%4,%5,%6,%7},{%8,%9},{%0,%1,%2,%3};" \
        : "+f"((c)[0]), "+f"((c)[1]), "+f"((c)[2]), "+f"((c)[3]) \
        : "r"((a)[0]), "r"((a)[1]), "r"((a)[2]), "r"((a)[3]), \
          "r"((b)[0]), "r"((b)[1]))

__device__ __forceinline__ uint32_t pack2(float x, float y) {
    __half2 h = __floats2half2_rn(x, y);
    uint32_t u;
    memcpy(&u, &h, 4);
    return u;
}

// ============================================================
// merged conversion kernel: fp16 A-conversions (MLP=4) + W transposes
// aconv part: each block covers 16384 elements (256 thr x 4 float4)
// ============================================================
#define ACONV_BPT 2048                       // blocks per input tensor (MLP=4)
#define ACONV_TOT (3 * ACONV_BPT)            // 6144
#define WQ_BLKS (64 * 64)                    // 4096
#define WK_BLKS (16 * 64)                    // 1024
#define WCONV_TOT (2 * WQ_BLKS + 2 * WK_BLKS) // 10240
#define CONV_TOT (ACONV_TOT + WCONV_TOT)

__global__ __launch_bounds__(256)
void conv_all(const float* __restrict__ q, const float* __restrict__ k,
              const float* __restrict__ v,
              __half* __restrict__ oq, __half* __restrict__ ok,
              __half* __restrict__ ov,
              const float* __restrict__ Wq, const float* __restrict__ Wk,
              const float* __restrict__ Wv, const float* __restrict__ Wo,
              __half* __restrict__ Oq, __half* __restrict__ Ok,
              __half* __restrict__ Ov, __half* __restrict__ Oo)
{
    int bid = blockIdx.x;
    if (bid < ACONV_TOT) {
        const float* A;
        __half* O;
        if (bid < ACONV_BPT)            { A = q; O = oq; }
        else if (bid < 2 * ACONV_BPT)   { A = k; O = ok; bid -= ACONV_BPT; }
        else                            { A = v; O = ov; bid -= 2 * ACONV_BPT; }
        // 4 independent float4 loads per thread (MLP=4)
        size_t base = (size_t)bid * 4096 + threadIdx.x * 4;   // float4 slots: tid + 256*j
        float4 v0 = *(const float4*)(A + (base + 0 * 1024));
        float4 v1 = *(const float4*)(A + (base + 1 * 1024));
        float4 v2 = *(const float4*)(A + (base + 2 * 1024));
        float4 v3 = *(const float4*)(A + (base + 3 * 1024));
        union { __half2 h[2]; uint2 u; } H;
        H.h[0] = __floats2half2_rn(v0.x, v0.y); H.h[1] = __floats2half2_rn(v0.z, v0.w);
        *(uint2*)(O + base + 0 * 1024) = H.u;
        H.h[0] = __floats2half2_rn(v1.x, v1.y); H.h[1] = __floats2half2_rn(v1.z, v1.w);
        *(uint2*)(O + base + 1 * 1024) = H.u;
        H.h[0] = __floats2half2_rn(v2.x, v2.y); H.h[1] = __floats2half2_rn(v2.z, v2.w);
        *(uint2*)(O + base + 2 * 1024) = H.u;
        H.h[0] = __floats2half2_rn(v3.x, v3.y); H.h[1] = __floats2half2_rn(v3.z, v3.w);
        *(uint2*)(O + base + 3 * 1024) = H.u;
        return;
    }
    bid -= ACONV_TOT;

    const float* W;
    __half* O;
    int Nd, nx;
    if (bid < WQ_BLKS) { W = Wq; O = Oq; Nd = HIDD; nx = 64; }
    else if (bid < WQ_BLKS + WK_BLKS) {
        W = Wk; O = Ok; Nd = KVD; nx = 16; bid -= WQ_BLKS;
    } else if (bid < WQ_BLKS + 2 * WK_BLKS) {
        W = Wv; O = Ov; Nd = KVD; nx = 16; bid -= WQ_BLKS + WK_BLKS;
    } else {
        W = Wo; O = Oo; Nd = HIDD; nx = 64; bid -= WQ_BLKS + 2 * WK_BLKS;
    }
    int n0 = (bid % nx) * 32;
    int k0 = (bid / nx) * 32;

    __shared__ float s[32][33];
    int r = threadIdx.x >> 5, c = threadIdx.x & 31;
    #pragma unroll
    for (int j = 0; j < 4; j++)
        s[r + 8 * j][c] = W[(size_t)(k0 + r + 8 * j) * Nd + n0 + c];
    __syncthreads();
    #pragma unroll
    for (int j = 0; j < 4; j++)
        O[(size_t)(n0 + r + 8 * j) * HIDD + k0 + c] = __float2half(s[c][r + 8 * j]);
}

// ============================================================
// shared GEMM body — block tile 256x128, warp tile 64x64 (validated R15/16)
// mode 0: fp32 out + bias; mode 1: +RoPE+scale fp16 [b,h,s,d]; mode 2: fp16 [b,h,s,d]
// ============================================================
#define GBK      64
#define NCH      (HIDD / GBK)        // 32
#define TILE_A   32768               // 256 rows x 128 bytes
#define TILE_BB  16384               // 128 rows x 128 bytes
#define STAGE_B  (TILE_A + TILE_BB)  // 49152
#define NSTAGE   3
#define GEMM_SMEM (NSTAGE * STAGE_B) // 147456

__device__ __forceinline__
void gemm_body(const __half* __restrict__ A, const __half* __restrict__ B,
               const float* __restrict__ bias, void* __restrict__ Cout,
               const float* __restrict__ cs, const float* __restrict__ sn,
               int N, float scale, int mode, int bx, int by)
{
    extern __shared__ char smem[];
    const uint32_t smem_base = smem_u32(smem);

    const int tid  = threadIdx.x;
    const int lane = tid & 31;
    const int warp = tid >> 5;
    const int bm = by * 256;
    const int bn = bx * 128;

    const int m0 = (warp >> 1) * 64;
    const int n0 = (warp & 1) * 64;

    float acc[4][8][4];
    #pragma unroll
    for (int mt = 0; mt < 4; mt++)
        #pragma unroll
        for (int nf = 0; nf < 8; nf++)
            #pragma unroll
            for (int q = 0; q < 4; q++) acc[mt][nf][q] = 0.f;

    const int a_row = m0 + (lane & 15);
    const int a_c8  = (lane >> 4);
    const int b_row = n0 + (lane & 7) + ((lane >> 4) << 3);
    const int b_c8  = (lane >> 3) & 1;

    auto load_stage = [&](int s, int k0) {
        uint32_t sb = smem_base + s * STAGE_B;
        #pragma unroll
        for (int t = 0; t < 8; t++) {
            int cc = tid + 256 * t;
            int r = cc >> 3, c = cc & 7;
            uint32_t off = (uint32_t)(r * 128 + ((c ^ (r & 7)) << 4));
            CP_ASYNC16(sb + off, A + (size_t)(bm + r) * HIDD + k0 + c * 8);
        }
        #pragma unroll
        for (int t = 0; t < 4; t++) {
            int cc = tid + 256 * t;
            int r = cc >> 3, c = cc & 7;
            uint32_t off = (uint32_t)(r * 128 + ((c ^ (r & 7)) << 4));
            CP_ASYNC16(sb + TILE_A + off, B + (size_t)(bn + r) * HIDD + k0 + c * 8);
        }
    };

    load_stage(0, 0);
    CP_COMMIT();
    load_stage(1, GBK);
    CP_COMMIT();

    for (int ch = 0; ch < NCH; ch++) {
        if (ch == NCH - 1) { CP_WAIT(0); } else { CP_WAIT(1); }
        __syncthreads();
        if (ch + 2 < NCH) {
            load_stage((ch + 2) % NSTAGE, (ch + 2) * GBK);
            CP_COMMIT();
        }

        const uint32_t sb = smem_base + (ch % NSTAGE) * STAGE_B;
        #pragma unroll
        for (int kk = 0; kk < 4; kk++) {
            uint32_t a[4][4];
            #pragma unroll
            for (int mt = 0; mt < 4; mt++) {
                int row = a_row + mt * 16;
                int ca = kk * 2 + a_c8;
                uint32_t addr = sb + (uint32_t)(row * 128 + ((ca ^ (row & 7)) << 4));
                LDSM4(a[mt][0], a[mt][1], a[mt][2], a[mt][3], addr);
            }
            #pragma unroll
            for (int nf2 = 0; nf2 < 4; nf2++) {
                int row = b_row + nf2 * 16;
                int cb = kk * 2 + b_c8;
                uint32_t addr = sb + TILE_A
                              + (uint32_t)(row * 128 + ((cb ^ (row & 7)) << 4));
                uint32_t b[2][2];
                LDSM4(b[0][0], b[0][1], b[1][0], b[1][1], addr);
                #pragma unroll
                for (int half = 0; half < 2; half++) {
                    const int nf = nf2 * 2 + half;
                    #pragma unroll
                    for (int mt = 0; mt < 4; mt++)
                        MMAF16(acc[mt][nf], a[mt], b[half]);
                }
            }
        }
        __syncthreads();
    }

    // ---- fused epilogue ----
    #pragma unroll
    for (int mt = 0; mt < 4; mt++) {
        int grow0 = bm + m0 + mt * 16 + (lane >> 2);
        #pragma unroll
        for (int nf = 0; nf < 8; nf++) {
            int gcol = bn + n0 + nf * 8 + (lane & 3) * 2;
            float2 bv = *(const float2*)(bias + gcol);
            #pragma unroll
            for (int hf = 0; hf < 2; hf++) {
                int r = grow0 + hf * 8;
                float x0 = acc[mt][nf][hf * 2 + 0] + bv.x;
                float x1 = acc[mt][nf][hf * 2 + 1] + bv.y;
                if (mode == 0) {
                    *(float2*)((float*)Cout + (size_t)r * N + gcol) =
                        make_float2(x0, x1);
                } else {
                    int bb = r / SS, s = r % SS;
                    int hh = gcol / HD, d = gcol % HD;
                    size_t o = ((size_t)(bb * (N / HD) + hh) * SS + s) * HD + d;
                    if (mode == 1) {
                        int p = d >> 1;
                        float c  = cs[s * 64 + p];
                        float si = sn[s * 64 + p];
                        float re = (x0 * c - x1 * si) * scale;
                        float im = (x0 * si + x1 * c) * scale;
                        *(__half2*)((__half*)Cout + o) = __floats2half2_rn(re, im);
                    } else {
                        *(__half2*)((__half*)Cout + o) = __floats2half2_rn(x0, x1);
                    }
                }
            }
        }
    }
}

// ---- merged Q+K+V projection launch ----
#define QG_BLKS 256   // 16 x 16
#define KG_BLKS 64    // 16 x 4

__global__ __launch_bounds__(256)
void gemm_qkv(const __half* __restrict__ Aq, const __half* __restrict__ Ak,
              const __half* __restrict__ Av,
              const __half* __restrict__ Wq, const __half* __restrict__ Wk,
              const __half* __restrict__ Wv,
              const float* __restrict__ bq, const float* __restrict__ bk,
              const float* __restrict__ bv,
              __half* __restrict__ qh, __half* __restrict__ kh,
              __half* __restrict__ vh,
              const float* __restrict__ cs, const float* __restrict__ sn,
              float qscale)
{
    int bid = blockIdx.x;
    if (bid < QG_BLKS) {
        gemm_body(Aq, Wq, bq, qh, cs, sn, HIDD, qscale, 1,
                  bid & 15, bid >> 4);
    } else if (bid < QG_BLKS + KG_BLKS) {
        bid -= QG_BLKS;
        gemm_body(Ak, Wk, bk, kh, cs, sn, KVD, 1.0f, 1,
                  bid & 3, bid >> 2);
    } else {
        bid -= QG_BLKS + KG_BLKS;
        gemm_body(Av, Wv, bv, vh, nullptr, nullptr, KVD, 1.0f, 2,
                  bid & 3, bid >> 2);
    }
}

// ---- O projection launch ----
__global__ __launch_bounds__(256)
void gemm_out(const __half* __restrict__ A, const __half* __restrict__ B,
              const float* __restrict__ bias, float* __restrict__ C)
{
    gemm_body(A, B, bias, C, nullptr, nullptr, HIDD, 1.0f, 0,
              blockIdx.x, blockIdx.y);
}

// ============================================================
// fp16 mma flash attention — softmax in base-2 (ex2.approx)
// Q pre-scaled by log2(e)/sqrt(D), so scores are already log2-domain.
// ============================================================
#define ATT_SMEM (5 * 32768)
#define SWZ(r, c) ((uint32_t)((r) * 256 + (((((c) ^ (r)) & 7) | ((c) & 8)) << 4)))

__global__ __launch_bounds__(256, 1)
void attn_f16(const __half* __restrict__ Qg, const __half* __restrict__ Kg,
              const __half* __restrict__ Vg, __half* __restrict__ ctx)
{
    extern __shared__ char smem[];
    const uint32_t sb = smem_u32(smem);
    const uint32_t Qs = sb;

    const int tid  = threadIdx.x;
    const int lane = tid & 31;
    const int warp = tid >> 5;
    const int qb = (int)gridDim.x - 1 - (int)blockIdx.x;
    const int h = blockIdx.y, b = blockIdx.z;
    const int kvh = h >> 2;

    const __half* Qbase = Qg + ((size_t)(b * NH + h) * SS + qb * 128) * HD;
    const __half* Kbase = Kg + ((size_t)(b * NKV + kvh) * SS) * HD;
    const __half* Vbase = Vg + ((size_t)(b * NKV + kvh) * SS) * HD;

    #pragma unroll
    for (int it = 0; it < 8; it++) {
        int lin = tid + 256 * it;
        int r = lin >> 4, c = lin & 15;
        CP_ASYNC16(Qs + SWZ(r, c), Qbase + r * HD + c * 8);
    }
    CP_COMMIT();

    auto load_kv = [&](int s, int k0) {
        uint32_t Kt = sb + 32768 + s * 65536;
        #pragma unroll
        for (int it = 0; it < 8; it++) {
            int lin = tid + 256 * it;
            int r = lin >> 4, c = lin & 15;
            uint32_t off = SWZ(r, c);
            CP_ASYNC16(Kt + off,         Kbase + (size_t)(k0 + r) * HD + c * 8);
            CP_ASYNC16(Kt + 32768 + off, Vbase + (size_t)(k0 + r) * HD + c * 8);
        }
    };
    load_kv(0, 0);
    CP_COMMIT();
    CP_WAIT(0);
    __syncthreads();

    uint32_t qa[8][4];
    {
        int ar = warp * 16 + (lane & 15);
        int ahi = lane >> 4;
        #pragma unroll
        for (int kk = 0; kk < 8; kk++) {
            uint32_t addr = Qs + SWZ(ar, kk * 2 + ahi);
            LDSM4(qa[kk][0], qa[kk][1], qa[kk][2], qa[kk][3], addr);
        }
    }

    float oacc[16][4];
    #pragma unroll
    for (int nf = 0; nf < 16; nf++)
        #pragma unroll
        for (int q = 0; q < 4; q++) oacc[nf][q] = 0.f;

    float m0 = -1e30f, m1 = -1e30f, l0 = 0.f, l1 = 0.f;
    const int row0 = lane >> 2;

    const int kb_row = (lane & 7) + ((lane >> 4) << 3);
    const int kb_c   = (lane >> 3) & 1;
    const int vb_row = (lane & 7) + (((lane >> 3) & 1) << 3);
    const int vb_c   = lane >> 4;

    const int ntiles = qb + 1;
    for (int t = 0; t < ntiles; t++) {
        if (t + 1 < ntiles) {
            load_kv((t + 1) & 1, (t + 1) * 128);
            CP_COMMIT();
            CP_WAIT(1);
        } else {
            CP_WAIT(0);
        }
        __syncthreads();
        const uint32_t Kt = sb + 32768 + (t & 1) * 65536;
        const uint32_t Vt = Kt + 32768;

        float sacc[16][4];
        #pragma unroll
        for (int nf = 0; nf < 16; nf++)
            #pragma unroll
            for (int q = 0; q < 4; q++) sacc[nf][q] = 0.f;

        #pragma unroll
        for (int kk = 0; kk < 8; kk++) {
            #pragma unroll
            for (int nf2 = 0; nf2 < 8; nf2++) {
                uint32_t bk[4];
                uint32_t addr = Kt + SWZ(nf2 * 16 + kb_row, kk * 2 + kb_c);
                LDSM4(bk[0], bk[1], bk[2], bk[3], addr);
                MMAF16(sacc[nf2 * 2],     qa[kk], bk);
                MMAF16(sacc[nf2 * 2 + 1], qa[kk], bk + 2);
            }
        }

        if (t == qb) {
            int qg = warp * 16 + row0;
            #pragma unroll
            for (int nf = 0; nf < 16; nf++) {
                int kg = nf * 8 + (lane & 3) * 2;
                if (kg > qg)         sacc[nf][0] = -1e30f;
                if (kg + 1 > qg)     sacc[nf][1] = -1e30f;
                if (kg > qg + 8)     sacc[nf][2] = -1e30f;
                if (kg + 1 > qg + 8) sacc[nf][3] = -1e30f;
            }
        }

        float mx0 = -1e30f, mx1 = -1e30f;
        #pragma unroll
        for (int nf = 0; nf < 16; nf++) {
            mx0 = fmaxf(mx0, fmaxf(sacc[nf][0], sacc[nf][1]));
            mx1 = fmaxf(mx1, fmaxf(sacc[nf][2], sacc[nf][3]));
        }
        mx0 = fmaxf(mx0, __shfl_xor_sync(0xffffffffu, mx0, 1));
        mx0 = fmaxf(mx0, __shfl_xor_sync(0xffffffffu, mx0, 2));
        mx1 = fmaxf(mx1, __shfl_xor_sync(0xffffffffu, mx1, 1));
        mx1 = fmaxf(mx1, __shfl_xor_sync(0xffffffffu, mx1, 2));
        float mn0 = fmaxf(m0, mx0), mn1 = fmaxf(m1, mx1);
        float al0 = ex2f(m0 - mn0), al1 = ex2f(m1 - mn1);
        m0 = mn0; m1 = mn1;
        float s0 = 0.f, s1 = 0.f;
        #pragma unroll
        for (int nf = 0; nf < 16; nf++) {
            sacc[nf][0] = ex2f(sacc[nf][0] - mn0); s0 += sacc[nf][0];
            sacc[nf][1] = ex2f(sacc[nf][1] - mn0); s0 += sacc[nf][1];
            sacc[nf][2] = ex2f(sacc[nf][2] - mn1); s1 += sacc[nf][2];
            sacc[nf][3] = ex2f(sacc[nf][3] - mn1); s1 += sacc[nf][3];
        }
        s0 += __shfl_xor_sync(0xffffffffu, s0, 1);
        s0 += __shfl_xor_sync(0xffffffffu, s0, 2);
        s1 += __shfl_xor_sync(0xffffffffu, s1, 1);
        s1 += __shfl_xor_sync(0xffffffffu, s1, 2);
        l0 = l0 * al0 + s0;
        l1 = l1 * al1 + s1;
        #pragma unroll
        for (int nf = 0; nf < 16; nf++) {
            oacc[nf][0] *= al0; oacc[nf][1] *= al0;
            oacc[nf][2] *= al1; oacc[nf][3] *= al1;
        }

        #pragma unroll
        for (int kc = 0; kc < 8; kc++) {
            uint32_t pa[4];
            pa[0] = pack2(sacc[2 * kc][0],     sacc[2 * kc][1]);
            pa[1] = pack2(sacc[2 * kc][2],     sacc[2 * kc][3]);
            pa[2] = pack2(sacc[2 * kc + 1][0], sacc[2 * kc + 1][1]);
            pa[3] = pack2(sacc[2 * kc + 1][2], sacc[2 * kc + 1][3]);
            #pragma unroll
            for (int dg2 = 0; dg2 < 8; dg2++) {
                uint32_t bv[4];
                uint32_t addr = Vt + SWZ(kc * 16 + vb_row, dg2 * 2 + vb_c);
                LDSM4T(bv[0], bv[1], bv[2], bv[3], addr);
                MMAF16(oacc[dg2 * 2],     pa, bv);
                MMAF16(oacc[dg2 * 2 + 1], pa, bv + 2);
            }
        }
        __syncthreads();
    }

    float inv0 = 1.f / l0, inv1 = 1.f / l1;
    int gr = qb * 128 + warp * 16 + row0;
    #pragma unroll
    for (int nf = 0; nf < 16; nf++) {
        int col = h * HD + nf * 8 + (lane & 3) * 2;
        *(__half2*)(ctx + (size_t)(b * SS + gr) * HIDD + col) =
            __floats2half2_rn(oacc[nf][0] * inv0, oacc[nf][1] * inv0);
        *(__half2*)(ctx + (size_t)(b * SS + gr + 8) * HIDD + col) =
            __floats2half2_rn(oacc[nf][2] * inv1, oacc[nf][3] * inv1);
    }
}

// ============================================================
// launch
// ============================================================
extern "C" void kernel_launch(void* const* d_in, const int* in_sizes, int n_in,
                              void* d_out, int out_size)
{
    const float* query = (const float*)d_in[0];
    const float* key   = (const float*)d_in[1];
    const float* value = (const float*)d_in[2];
    const float* fcos  = (const float*)d_in[4];
    const float* fsin  = (const float*)d_in[5];
    const float* Wq = (const float*)d_in[6];
    const float* bq = (const float*)d_in[7];
    const float* Wk = (const float*)d_in[8];
    const float* bk = (const float*)d_in[9];
    const float* Wv = (const float*)d_in[10];
    const float* bv = (const float*)d_in[11];
    const float* Wo = (const float*)d_in[12];
    const float* bo = (const float*)d_in[13];
    float* out = (float*)d_out;

    __half *Afq, *Afk, *Afv, *Wfq, *Wfk, *Wfv, *Wfo, *qh, *kh, *vh, *ctxh;
    cudaGetSymbolAddress((void**)&Afq,  g_Afq);
    cudaGetSymbolAddress((void**)&Afk,  g_Afk);
    cudaGetSymbolAddress((void**)&Afv,  g_Afv);
    cudaGetSymbolAddress((void**)&Wfq,  g_Wfq);
    cudaGetSymbolAddress((void**)&Wfk,  g_Wfk);
    cudaGetSymbolAddress((void**)&Wfv,  g_Wfv);
    cudaGetSymbolAddress((void**)&Wfo,  g_Wfo);
    cudaGetSymbolAddress((void**)&qh,   g_qh);
    cudaGetSymbolAddress((void**)&kh,   g_kh);
    cudaGetSymbolAddress((void**)&vh,   g_vh);
    cudaGetSymbolAddress((void**)&ctxh, g_ctxh);

    cudaFuncSetAttribute(gemm_qkv,
                         cudaFuncAttributeMaxDynamicSharedMemorySize, GEMM_SMEM);
    cudaFuncSetAttribute(gemm_out,
                         cudaFuncAttributeMaxDynamicSharedMemorySize, GEMM_SMEM);
    cudaFuncSetAttribute(attn_f16,
                         cudaFuncAttributeMaxDynamicSharedMemorySize, ATT_SMEM);

    // log2(e) / sqrt(128): softmax computed in base-2 (ex2)
    const float QSCALE2 = 0.12751743558f;

    // 1) all conversions in one launch (A tensors MLP=4 + W transposes)
    conv_all<<<CONV_TOT, 256>>>(query, key, value, Afq, Afk, Afv,
                                Wq, Wk, Wv, Wo, Wfq, Wfk, Wfv, Wfo);

    // 2) merged Q/K/V projections (+RoPE / layout epilogues)
    gemm_qkv<<<QG_BLKS + 2 * KG_BLKS, 256, GEMM_SMEM>>>(
        Afq, Afk, Afv, Wfq, Wfk, Wfv, bq, bk, bv,
        qh, kh, vh, fcos, fsin, QSCALE2);

    // 3) attention (base-2 softmax)
    attn_f16<<<dim3(SS / 128, NH, BB), 256, ATT_SMEM>>>(qh, kh, vh, ctxh);

    // 4) O projection (fp32 out)
    gemm_out<<<dim3(HIDD / 128, MR / 256), 256, GEMM_SMEM>>>(ctxh, Wfo, bo, out);
}